// round 6
// baseline (speedup 1.0000x reference)
#include <cuda_runtime.h>
#include <math.h>
#include <stdint.h>

#define G 296                    // 2 CTAs/SM x 148 SMs
#define NTHR 256
#define STAGES 4
#define TILE_BYTES 16384
#define TILE_ELEMS 4096
#define TILE_V4 1024
#define SAMP_BINS 1024
#define FINE_BINS 1024
#define MAX_POS (1 << 20)
#define POS_CAP 5120
#define SAMP_LO (-12.0f)
#define SAMP_W  (24.0f / SAMP_BINS)

static __device__ int                g_pos_n;
static __device__ int                g_pos_idx[MAX_POS];
static __device__ float              g_pos_val[MAX_POS];
static __device__ int                g_samp_hist[SAMP_BINS];
static __device__ int                g_samp_pos;
static __device__ float              g_Tlo, g_Thi;
static __device__ unsigned long long g_cnt_above;
static __device__ double             g_loss_above, g_sig_above;
static __device__ int                g_fine_cnt[FINE_BINS];
static __device__ float              g_fine_loss[FINE_BINS];
static __device__ float              g_fine_sig[FINE_BINS];

__device__ __forceinline__ float softplus_acc(float x) {
    return fmaxf(x, 0.0f) + log1pf(__expf(-fabsf(x)));
}
__device__ __forceinline__ float softplus_fast(float x) {
    return fmaxf(x, 0.0f) + __logf(1.0f + __expf(-fabsf(x)));
}
__device__ __forceinline__ float sigm_fast(float x) {
    return __fdividef(1.0f, 1.0f + __expf(-x));
}

// ---- TMA 1D bulk + mbarrier helpers --------------------------------------
__device__ __forceinline__ uint32_t smaddr(const void* p) {
    return (uint32_t)__cvta_generic_to_shared(p);
}
__device__ __forceinline__ void mbar_init(uint32_t a, uint32_t cnt) {
    asm volatile("mbarrier.init.shared.b64 [%0], %1;" :: "r"(a), "r"(cnt) : "memory");
}
__device__ __forceinline__ void mbar_expect_tx(uint32_t a, uint32_t bytes) {
    asm volatile("mbarrier.arrive.expect_tx.shared.b64 _, [%0], %1;" :: "r"(a), "r"(bytes) : "memory");
}
__device__ __forceinline__ void bulk_g2s(uint32_t dst, const void* gsrc, uint32_t bytes, uint32_t mbar) {
    asm volatile(
        "cp.async.bulk.shared::cluster.global.mbarrier::complete_tx::bytes [%0], [%1], %2, [%3];"
        :: "r"(dst), "l"(gsrc), "r"(bytes), "r"(mbar) : "memory");
}
__device__ __forceinline__ void mbar_wait(uint32_t a, uint32_t parity) {
    asm volatile(
        "{\n\t"
        ".reg .pred P1;\n\t"
        "WAIT_LOOP_%=:\n\t"
        "mbarrier.try_wait.parity.acquire.cta.shared::cta.b64 P1, [%0], %1, 0x989680;\n\t"
        "@P1 bra.uni WAIT_DONE_%=;\n\t"
        "bra.uni WAIT_LOOP_%=;\n\t"
        "WAIT_DONE_%=:\n\t"
        "}"
        :: "r"(a), "r"(parity) : "memory");
}

// ---------------------------------------------------------------------------
__global__ void k_init() {
    int i = blockIdx.x * blockDim.x + threadIdx.x;
    if (i == 0) {
        g_pos_n = 0;
        g_samp_pos = 0;
        g_cnt_above = 0ull;
        g_loss_above = 0.0;
        g_sig_above = 0.0;
    }
    if (i < SAMP_BINS) g_samp_hist[i] = 0;
    if (i < FINE_BINS) {
        g_fine_cnt[i] = 0;
        g_fine_loss[i] = 0.0f;
        g_fine_sig[i] = 0.0f;
    }
}

// ---------------------------------------------------------------------------
// k_sample: 1/16 gather of preds+targs -> coarse hist of negatives + sampled
// positive count (for n_pos ESTIMATE; exact n_pos comes later from k_stream)
// ---------------------------------------------------------------------------
__global__ __launch_bounds__(NTHR) void k_sample(
    const float4* __restrict__ preds4, const int4* __restrict__ targs4, int n)
{
    __shared__ int s_hist[SAMP_BINS];
    __shared__ int s_pos;
    const int tid = threadIdx.x;
    for (int i = tid; i < SAMP_BINS; i += NTHR) s_hist[i] = 0;
    if (tid == 0) s_pos = 0;
    __syncthreads();

    const int n4 = n >> 2;
    const int TOT = gridDim.x * NTHR;
    const float scale = (float)SAMP_BINS / 24.0f;
    int myp = 0;
    for (int s = blockIdx.x * NTHR + tid; s < (n4 >> 4); s += TOT) {
        int idx4 = s << 4;           // every 16th float4 => 1/16 of elements
        float4 p = preds4[idx4];
        int4   t = targs4[idx4];
        if (!t.x) { int b = (int)((p.x - SAMP_LO) * scale); b = max(0, min(SAMP_BINS - 1, b)); atomicAdd(&s_hist[b], 1); } else myp++;
        if (!t.y) { int b = (int)((p.y - SAMP_LO) * scale); b = max(0, min(SAMP_BINS - 1, b)); atomicAdd(&s_hist[b], 1); } else myp++;
        if (!t.z) { int b = (int)((p.z - SAMP_LO) * scale); b = max(0, min(SAMP_BINS - 1, b)); atomicAdd(&s_hist[b], 1); } else myp++;
        if (!t.w) { int b = (int)((p.w - SAMP_LO) * scale); b = max(0, min(SAMP_BINS - 1, b)); atomicAdd(&s_hist[b], 1); } else myp++;
    }
    if (myp) atomicAdd(&s_pos, myp);
    __syncthreads();
    if (tid == 0 && s_pos) atomicAdd(&g_samp_pos, s_pos);
    for (int i = tid; i < SAMP_BINS; i += NTHR) {
        int c = s_hist[i];
        if (c) atomicAdd(&g_samp_hist[i], c);
    }
}

// ---------------------------------------------------------------------------
// k_pick (1 block): estimated n_hns -> bracketing window [Tlo,Thi].
// Margins (0.65x / 1.5x) absorb both quantile and n_pos sampling error.
// ---------------------------------------------------------------------------
__global__ void k_pick(long long N) {
    __shared__ long long suf[SAMP_BINS];
    __shared__ int sh_bhi, sh_blo;
    int t = threadIdx.x;
    suf[t] = (long long)g_samp_hist[t];
    if (t == 0) { sh_bhi = SAMP_BINS; sh_blo = -1; }
    __syncthreads();
    for (int off = 1; off < SAMP_BINS; off <<= 1) {
        long long v = (t + off < SAMP_BINS) ? suf[t + off] : 0;
        __syncthreads();
        suf[t] += v;
        __syncthreads();
    }
    long long pos_est = 16LL * (long long)g_samp_pos;
    long long neg_est = N - pos_est;
    long long nhns = (pos_est > 0) ? min(pos_est * 30LL, neg_est)
                                   : (long long)(0.1 * (double)neg_est);
    long long est = 16LL * suf[t];
    if (est * 100 <= nhns * 65)  atomicMin(&sh_bhi, t);
    if (est * 10  >= nhns * 15)  atomicMax(&sh_blo, t);
    __syncthreads();
    if (t == 0) {
        int bhi = sh_bhi, blo = sh_blo;
        if (bhi > SAMP_BINS - 1) bhi = SAMP_BINS - 1;
        if (bhi < 1) bhi = 1;
        if (blo < 0) blo = 0;
        if (blo >= bhi) blo = bhi - 1;
        g_Thi = SAMP_LO + (float)bhi * SAMP_W;
        g_Tlo = SAMP_LO + (float)blo * SAMP_W;
    }
}

// ---------------------------------------------------------------------------
// k_stream: fused single pass. Each CTA interleaves preds-tiles and
// targs-tiles through one 4-stage TMA ring (134MB total, one ramp).
//   P-tile: sums above Thi (regs) + fine hist (smem)
//   T-tile: positive indices -> s_pos -> g_pos_idx (1 global atomic per flush)
// ---------------------------------------------------------------------------
__global__ __launch_bounds__(NTHR) void k_stream(
    const float* __restrict__ preds, const int* __restrict__ targs, int n)
{
    __shared__ alignas(128) uint4 buf[STAGES][TILE_V4];   // 64KB
    __shared__ uint64_t mbar[STAGES];
    __shared__ int   s_cnt[FINE_BINS];
    __shared__ float s_loss[FINE_BINS];
    __shared__ float s_sig[FINE_BINS];
    __shared__ int   s_pos[POS_CAP];                       // 20KB
    __shared__ int   s_pcnt, s_base;
    __shared__ float rwl[8], rws[8];
    __shared__ int   rwc[8];

    const int tid = threadIdx.x;
    const int b0 = blockIdx.x;
    for (int i = tid; i < FINE_BINS; i += NTHR) {
        s_cnt[i] = 0; s_loss[i] = 0.0f; s_sig[i] = 0.0f;
    }
    if (tid == 0) {
        s_pcnt = 0;
        #pragma unroll
        for (int s = 0; s < STAGES; s++) mbar_init(smaddr(&mbar[s]), 1);
        asm volatile("fence.proxy.async.shared::cta;" ::: "memory");
    }
    __syncthreads();

    const float Tlo = g_Tlo, Thi = g_Thi;
    const float fscale = (float)FINE_BINS / (Thi - Tlo);
    int cnt = 0;
    float ls = 0.0f, ss = 0.0f;

    const int ntiles = n / TILE_ELEMS;          // per array
    const int np = (ntiles > b0) ? (ntiles - b0 + G - 1) / G : 0;
    const int nt = np;                          // same tiling both arrays
    const int total = np + nt;
    const int m2 = 2 * min(np, nt);

    // map logical iteration j -> (kind: 0=preds 1=targs, local tile index)
    auto issue = [&](int j, int stage) {
        int kind, li;
        if (j < m2) { kind = j & 1; li = j >> 1; }
        else if (np > nt) { kind = 0; li = j - nt; }
        else { kind = 1; li = j - np; }
        int g = b0 + li * G;
        const char* src = kind ? (const char*)targs : (const char*)preds;
        uint32_t mb = smaddr(&mbar[stage]);
        mbar_expect_tx(mb, TILE_BYTES);
        bulk_g2s(smaddr(&buf[stage][0]), src + (size_t)g * TILE_BYTES, TILE_BYTES, mb);
    };

    if (tid == 0) {
        for (int s = 0; s < STAGES && s < total; s++) issue(s, s);
    }

    for (int j = 0; j < total; j++) {
        int st = j % STAGES;
        int parity = (j / STAGES) & 1;
        mbar_wait(smaddr(&mbar[st]), parity);

        int kind, li;
        if (j < m2) { kind = j & 1; li = j >> 1; }
        else if (np > nt) { kind = 0; li = j - nt; }
        else { kind = 1; li = j - np; }
        int g = b0 + li * G;

        if (kind == 0) {
            const float4* fb = reinterpret_cast<const float4*>(&buf[st][0]);
            #pragma unroll
            for (int k = 0; k < 4; k++) {
                float4 p = fb[tid + k * NTHR];
                #pragma unroll
                for (int c = 0; c < 4; c++) {
                    float v = (c == 0) ? p.x : (c == 1) ? p.y : (c == 2) ? p.z : p.w;
                    if (v > Tlo) {
                        float sp = softplus_fast(v);
                        float sg = sigm_fast(v);
                        if (v > Thi) {
                            cnt++; ls += sp; ss += sg;
                        } else {
                            int fb2 = min((int)((v - Tlo) * fscale), FINE_BINS - 1);
                            atomicAdd(&s_cnt[fb2], 1);
                            atomicAdd(&s_loss[fb2], sp);
                            atomicAdd(&s_sig[fb2], sg);
                        }
                    }
                }
            }
            __syncthreads();
        } else {
            const int4* ib = reinterpret_cast<const int4*>(&buf[st][0]);
            int ebase = g * TILE_ELEMS;
            #pragma unroll
            for (int k = 0; k < 4; k++) {
                int v = tid + k * NTHR;
                int4 a = ib[v];
                if (a.x | a.y | a.z | a.w) {
                    int e = ebase + v * 4;
                    if (a.x) { int s = atomicAdd(&s_pcnt, 1); if (s < POS_CAP) s_pos[s] = e + 0; }
                    if (a.y) { int s = atomicAdd(&s_pcnt, 1); if (s < POS_CAP) s_pos[s] = e + 1; }
                    if (a.z) { int s = atomicAdd(&s_pcnt, 1); if (s < POS_CAP) s_pos[s] = e + 2; }
                    if (a.w) { int s = atomicAdd(&s_pcnt, 1); if (s < POS_CAP) s_pos[s] = e + 3; }
                }
            }
            __syncthreads();
            if (s_pcnt > POS_CAP - TILE_ELEMS) {   // keep room for next T tile
                int c0 = min(s_pcnt, POS_CAP);
                if (tid == 0) s_base = atomicAdd(&g_pos_n, c0);
                __syncthreads();
                for (int i = tid; i < c0; i += NTHR) {
                    int d = s_base + i;
                    if (d < MAX_POS) g_pos_idx[d] = s_pos[i];
                }
                __syncthreads();
                if (tid == 0) s_pcnt = 0;
                __syncthreads();
            }
        }

        if (tid == 0 && j + STAGES < total) issue(j + STAGES, st);
    }

    // tail elements (n not multiple of TILE_ELEMS), parallel over block 0
    if (b0 == 0) {
        for (int i = ntiles * TILE_ELEMS + tid; i < n; i += NTHR) {
            float v = preds[i];
            if (v > Tlo) {
                float sp = softplus_fast(v);
                float sg = sigm_fast(v);
                if (v > Thi) { cnt++; ls += sp; ss += sg; }
                else {
                    int fb2 = min((int)((v - Tlo) * fscale), FINE_BINS - 1);
                    atomicAdd(&s_cnt[fb2], 1);
                    atomicAdd(&s_loss[fb2], sp);
                    atomicAdd(&s_sig[fb2], sg);
                }
            }
            if (targs[i]) {
                int id = atomicAdd(&g_pos_n, 1);
                if (id < MAX_POS) g_pos_idx[id] = i;
            }
        }
    }

    // final positive flush
    __syncthreads();
    {
        int c0 = min(s_pcnt, POS_CAP);
        if (c0 > 0) {
            if (tid == 0) s_base = atomicAdd(&g_pos_n, c0);
            __syncthreads();
            for (int i = tid; i < c0; i += NTHR) {
                int d = s_base + i;
                if (d < MAX_POS) g_pos_idx[d] = s_pos[i];
            }
        }
    }

    // block reduction of above-threshold sums (warp shuffle + tiny smem)
    for (int off = 16; off > 0; off >>= 1) {
        cnt += __shfl_down_sync(0xffffffffu, cnt, off);
        ls  += __shfl_down_sync(0xffffffffu, ls, off);
        ss  += __shfl_down_sync(0xffffffffu, ss, off);
    }
    int wid = tid >> 5, lid = tid & 31;
    if (lid == 0) { rwc[wid] = cnt; rwl[wid] = ls; rws[wid] = ss; }
    __syncthreads();
    if (tid == 0) {
        int tc = 0; float tl = 0.0f, ts = 0.0f;
        #pragma unroll
        for (int w = 0; w < 8; w++) { tc += rwc[w]; tl += rwl[w]; ts += rws[w]; }
        if (tc) atomicAdd(&g_cnt_above, (unsigned long long)tc);
        atomicAdd(&g_loss_above, (double)tl);
        atomicAdd(&g_sig_above,  (double)ts);
    }
    // merge fine histogram (skip empty bins)
    for (int i = tid; i < FINE_BINS; i += NTHR) {
        int c = s_cnt[i];
        if (c) {
            atomicAdd(&g_fine_cnt[i], c);
            atomicAdd(&g_fine_loss[i], s_loss[i]);
            atomicAdd(&g_fine_sig[i], s_sig[i]);
        }
    }
}

// ---------------------------------------------------------------------------
// k_gather: parallel prefetch of positive values (kills k_final's latency chain)
// ---------------------------------------------------------------------------
__global__ void k_gather(const float* __restrict__ preds) {
    int n_pos = min(g_pos_n, MAX_POS);
    for (int i = blockIdx.x * blockDim.x + threadIdx.x; i < n_pos;
         i += gridDim.x * blockDim.x)
        g_pos_val[i] = preds[g_pos_idx[i]];
}

// ---------------------------------------------------------------------------
// k_final (1 block): exact nhns, positive correction, threshold bin, result
// ---------------------------------------------------------------------------
__global__ void k_final(float* __restrict__ out, int out_size, long long N) {
    __shared__ int       s_cnt[FINE_BINS];
    __shared__ float     s_loss[FINE_BINS];
    __shared__ float     s_sig[FINE_BINS];
    __shared__ long long suf[FINE_BINS];
    __shared__ double    red1[1024], red2[1024];
    __shared__ int       sh_adj_cnt;
    __shared__ double    sh_adj_loss, sh_adj_sig;
    __shared__ int       sh_bstar;
    __shared__ float     sh_result;

    int t = threadIdx.x;
    s_cnt[t]  = g_fine_cnt[t];
    s_loss[t] = g_fine_loss[t];
    s_sig[t]  = g_fine_sig[t];
    if (t == 0) { sh_adj_cnt = 0; sh_adj_loss = 0.0; sh_adj_sig = 0.0; sh_bstar = -1; }
    __syncthreads();

    const float Tlo = g_Tlo, Thi = g_Thi;
    const float fscale = (float)FINE_BINS / (Thi - Tlo);
    int n_pos = min(g_pos_n, MAX_POS);

    double ploss = 0.0, psig = 0.0;
    for (int i = t; i < n_pos; i += blockDim.x) {
        float q  = g_pos_val[i];
        float sp = softplus_acc(q);
        float sg = sigm_fast(q);
        ploss += (double)(sp - q);
        psig  += (double)sg;
        if (q > Thi) {
            float spf = softplus_fast(q);   // mirror k_stream fast math
            atomicAdd(&sh_adj_cnt, 1);
            atomicAdd(&sh_adj_loss, (double)spf);
            atomicAdd(&sh_adj_sig,  (double)sg);
        } else if (q > Tlo) {
            float spf = softplus_fast(q);
            int fb = min((int)((q - Tlo) * fscale), FINE_BINS - 1);
            atomicSub(&s_cnt[fb], 1);
            atomicAdd(&s_loss[fb], -spf);
            atomicAdd(&s_sig[fb],  -sg);
        }
    }
    red1[t] = ploss; red2[t] = psig;
    __syncthreads();
    for (int off = 512; off > 0; off >>= 1) {
        if (t < off) { red1[t] += red1[t + off]; red2[t] += red2[t + off]; }
        __syncthreads();
    }
    double pos_loss = red1[0];
    double pos_sig  = red2[0];
    __syncthreads();

    suf[t] = (long long)s_cnt[t];
    __syncthreads();
    for (int off = 1; off < FINE_BINS; off <<= 1) {
        long long v = (t + off < FINE_BINS) ? suf[t + off] : 0;
        __syncthreads();
        suf[t] += v;
        __syncthreads();
    }

    long long n_posL = (long long)n_pos;
    long long n_neg = N - n_posL;
    long long nhns = (n_posL > 0) ? min(n_posL * 30LL, n_neg)
                                  : (long long)(0.1 * (double)n_neg);
    long long cnt_above = (long long)g_cnt_above - (long long)sh_adj_cnt;

    if (cnt_above + suf[t] >= nhns) atomicMax(&sh_bstar, t);
    __syncthreads();
    int bstar = sh_bstar;

    double fl = 0.0, fs = 0.0;
    if (t > bstar) { fl = (double)s_loss[t]; fs = (double)s_sig[t]; }
    red1[t] = fl; red2[t] = fs;
    __syncthreads();
    for (int off = 512; off > 0; off >>= 1) {
        if (t < off) { red1[t] += red1[t + off]; red2[t] += red2[t + off]; }
        __syncthreads();
    }

    if (t == 0) {
        double neg_loss = g_loss_above - sh_adj_loss + red1[0];
        double neg_sig  = g_sig_above  - sh_adj_sig  + red2[0];
        if (bstar >= 0 && bstar < FINE_BINS && s_cnt[bstar] > 0) {
            long long taken = cnt_above + (suf[bstar] - (long long)s_cnt[bstar]);
            long long r = nhns - taken;
            if (r < 0) r = 0;
            if (r > (long long)s_cnt[bstar]) r = (long long)s_cnt[bstar];
            double frac = (double)r / (double)s_cnt[bstar];
            neg_loss += frac * (double)s_loss[bstar];
            neg_sig  += frac * (double)s_sig[bstar];
        }
        double total_loss = neg_loss + pos_loss;
        double mean_loss  = total_loss / (double)(nhns + n_posL);
        double inter = pos_sig;
        double denom = neg_sig + pos_sig + (double)n_posL;
        double dice  = 1.0 - (2.0 * inter + 1e-10) / (denom + 1e-10);
        sh_result = (float)(dice + mean_loss);
    }
    __syncthreads();
    float r = sh_result;
    for (int i = t; i < out_size; i += blockDim.x) out[i] = r;
}

// ---------------------------------------------------------------------------
extern "C" void kernel_launch(void* const* d_in, const int* in_sizes, int n_in,
                              void* d_out, int out_size) {
    const float* preds = (const float*)d_in[0];
    const int*   targs = (const int*)d_in[1];
    int n = in_sizes[0];

    k_init<<<4, 256>>>();
    k_sample<<<G, NTHR>>>((const float4*)preds, (const int4*)targs, n);
    k_pick<<<1, 1024>>>((long long)n);
    k_stream<<<G, NTHR>>>(preds, targs, n);
    k_gather<<<128, 256>>>(preds);
    k_final<<<1, 1024>>>((float*)d_out, out_size, (long long)n);
}

// round 7
// speedup vs baseline: 1.6609x; 1.6609x over previous
#include <cuda_runtime.h>
#include <math.h>
#include <stdint.h>

#define G 296                    // 2 CTAs/SM x 148 SMs
#define NTHR 256
#define STAGES 4
#define TILE_BYTES 16384
#define TILE_ELEMS 4096
#define TILE_V4 1024
#define SAMP_BINS 1024
#define FINE_BINS 1024
#define MAX_POS (1 << 20)
#define POS_CAP 5120
#define SAMP_LO (-12.0f)
#define SAMP_W  (24.0f / SAMP_BINS)

static __device__ int                g_pos_n;
static __device__ int                g_pos_idx[MAX_POS];
static __device__ float              g_pos_val[MAX_POS];
static __device__ int                g_samp_hist[SAMP_BINS];
static __device__ int                g_samp_pos;
static __device__ float              g_Tlo, g_Thi;
static __device__ unsigned long long g_cnt_above;
static __device__ double             g_loss_above, g_sig_above;
static __device__ int                g_fine_cnt[FINE_BINS];
static __device__ float              g_fine_loss[FINE_BINS];
static __device__ float              g_fine_sig[FINE_BINS];

__device__ __forceinline__ float softplus_acc(float x) {
    return fmaxf(x, 0.0f) + log1pf(__expf(-fabsf(x)));
}
__device__ __forceinline__ float softplus_fast(float x) {
    return fmaxf(x, 0.0f) + __logf(1.0f + __expf(-fabsf(x)));
}
__device__ __forceinline__ float sigm_fast(float x) {
    return __fdividef(1.0f, 1.0f + __expf(-x));
}

// ---- TMA 1D bulk + mbarrier helpers --------------------------------------
__device__ __forceinline__ uint32_t smaddr(const void* p) {
    return (uint32_t)__cvta_generic_to_shared(p);
}
__device__ __forceinline__ void mbar_init(uint32_t a, uint32_t cnt) {
    asm volatile("mbarrier.init.shared.b64 [%0], %1;" :: "r"(a), "r"(cnt) : "memory");
}
__device__ __forceinline__ void mbar_expect_tx(uint32_t a, uint32_t bytes) {
    asm volatile("mbarrier.arrive.expect_tx.shared.b64 _, [%0], %1;" :: "r"(a), "r"(bytes) : "memory");
}
__device__ __forceinline__ void bulk_g2s(uint32_t dst, const void* gsrc, uint32_t bytes, uint32_t mbar) {
    asm volatile(
        "cp.async.bulk.shared::cluster.global.mbarrier::complete_tx::bytes [%0], [%1], %2, [%3];"
        :: "r"(dst), "l"(gsrc), "r"(bytes), "r"(mbar) : "memory");
}
__device__ __forceinline__ void mbar_wait(uint32_t a, uint32_t parity) {
    asm volatile(
        "{\n\t"
        ".reg .pred P1;\n\t"
        "WAIT_LOOP_%=:\n\t"
        "mbarrier.try_wait.parity.acquire.cta.shared::cta.b64 P1, [%0], %1, 0x989680;\n\t"
        "@P1 bra.uni WAIT_DONE_%=;\n\t"
        "bra.uni WAIT_LOOP_%=;\n\t"
        "WAIT_DONE_%=:\n\t"
        "}"
        :: "r"(a), "r"(parity) : "memory");
}

// ---------------------------------------------------------------------------
__global__ void k_init() {
    int i = blockIdx.x * blockDim.x + threadIdx.x;
    if (i == 0) {
        g_pos_n = 0;
        g_samp_pos = 0;
        g_cnt_above = 0ull;
        g_loss_above = 0.0;
        g_sig_above = 0.0;
    }
    if (i < SAMP_BINS) g_samp_hist[i] = 0;
    if (i < FINE_BINS) {
        g_fine_cnt[i] = 0;
        g_fine_loss[i] = 0.0f;
        g_fine_sig[i] = 0.0f;
    }
}

// ---------------------------------------------------------------------------
// k_sample: COALESCED 1/16 sample. A "segment" = NTHR consecutive float4s
// (1024 elements). We take every 16th segment; each thread reads one float4
// per segment -> fully coalesced, ~8.4MB total traffic.
// ---------------------------------------------------------------------------
__global__ __launch_bounds__(NTHR) void k_sample(
    const float4* __restrict__ preds4, const int4* __restrict__ targs4, int n)
{
    __shared__ int s_hist[SAMP_BINS];
    __shared__ int s_pos;
    const int tid = threadIdx.x;
    for (int i = tid; i < SAMP_BINS; i += NTHR) s_hist[i] = 0;
    if (tid == 0) s_pos = 0;
    __syncthreads();

    const int n4 = n >> 2;
    const int nseg = n4 / (16 * NTHR);    // segments we sample (1 in 16)
    const float scale = (float)SAMP_BINS / 24.0f;
    int myp = 0;

    for (int s = blockIdx.x; s < nseg; s += gridDim.x) {
        int base = s * 16 * NTHR;         // start of the sampled segment
        int idx4 = base + tid;
        float4 p = __ldcs(&preds4[idx4]);
        int4   t = __ldcs(&targs4[idx4]);
        if (!t.x) { int b = (int)((p.x - SAMP_LO) * scale); b = max(0, min(SAMP_BINS - 1, b)); atomicAdd(&s_hist[b], 1); } else myp++;
        if (!t.y) { int b = (int)((p.y - SAMP_LO) * scale); b = max(0, min(SAMP_BINS - 1, b)); atomicAdd(&s_hist[b], 1); } else myp++;
        if (!t.z) { int b = (int)((p.z - SAMP_LO) * scale); b = max(0, min(SAMP_BINS - 1, b)); atomicAdd(&s_hist[b], 1); } else myp++;
        if (!t.w) { int b = (int)((p.w - SAMP_LO) * scale); b = max(0, min(SAMP_BINS - 1, b)); atomicAdd(&s_hist[b], 1); } else myp++;
    }
    if (myp) atomicAdd(&s_pos, myp);
    __syncthreads();
    if (tid == 0 && s_pos) atomicAdd(&g_samp_pos, s_pos);
    for (int i = tid; i < SAMP_BINS; i += NTHR) {
        int c = s_hist[i];
        if (c) atomicAdd(&g_samp_hist[i], c);
    }
}

// ---------------------------------------------------------------------------
// k_pick (1 block): estimated n_hns -> bracketing window [Tlo,Thi].
// Margins (0.65x / 1.5x) absorb quantile + n_pos sampling error.
// ---------------------------------------------------------------------------
__global__ void k_pick(long long N) {
    __shared__ long long suf[SAMP_BINS];
    __shared__ int sh_bhi, sh_blo;
    int t = threadIdx.x;
    suf[t] = (long long)g_samp_hist[t];
    if (t == 0) { sh_bhi = SAMP_BINS; sh_blo = -1; }
    __syncthreads();
    for (int off = 1; off < SAMP_BINS; off <<= 1) {
        long long v = (t + off < SAMP_BINS) ? suf[t + off] : 0;
        __syncthreads();
        suf[t] += v;
        __syncthreads();
    }
    long long pos_est = 16LL * (long long)g_samp_pos;
    long long neg_est = N - pos_est;
    long long nhns = (pos_est > 0) ? min(pos_est * 30LL, neg_est)
                                   : (long long)(0.1 * (double)neg_est);
    long long est = 16LL * suf[t];
    if (est * 100 <= nhns * 65)  atomicMin(&sh_bhi, t);
    if (est * 10  >= nhns * 15)  atomicMax(&sh_blo, t);
    __syncthreads();
    if (t == 0) {
        int bhi = sh_bhi, blo = sh_blo;
        if (bhi > SAMP_BINS - 1) bhi = SAMP_BINS - 1;
        if (bhi < 1) bhi = 1;
        if (blo < 0) blo = 0;
        if (blo >= bhi) blo = bhi - 1;
        g_Thi = SAMP_LO + (float)bhi * SAMP_W;
        g_Tlo = SAMP_LO + (float)blo * SAMP_W;
    }
}

// ---------------------------------------------------------------------------
// k_stream: fused single pass. Each CTA interleaves preds-tiles and
// targs-tiles through one 4-stage TMA ring (134MB total, one ramp).
// ---------------------------------------------------------------------------
__global__ __launch_bounds__(NTHR) void k_stream(
    const float* __restrict__ preds, const int* __restrict__ targs, int n)
{
    __shared__ alignas(128) uint4 buf[STAGES][TILE_V4];   // 64KB
    __shared__ uint64_t mbar[STAGES];
    __shared__ int   s_cnt[FINE_BINS];
    __shared__ float s_loss[FINE_BINS];
    __shared__ float s_sig[FINE_BINS];
    __shared__ int   s_pos[POS_CAP];                       // 20KB
    __shared__ int   s_pcnt, s_base;
    __shared__ float rwl[8], rws[8];
    __shared__ int   rwc[8];

    const int tid = threadIdx.x;
    const int b0 = blockIdx.x;
    for (int i = tid; i < FINE_BINS; i += NTHR) {
        s_cnt[i] = 0; s_loss[i] = 0.0f; s_sig[i] = 0.0f;
    }
    if (tid == 0) {
        s_pcnt = 0;
        #pragma unroll
        for (int s = 0; s < STAGES; s++) mbar_init(smaddr(&mbar[s]), 1);
        asm volatile("fence.proxy.async.shared::cta;" ::: "memory");
    }
    __syncthreads();

    const float Tlo = g_Tlo, Thi = g_Thi;
    const float fscale = (float)FINE_BINS / (Thi - Tlo);
    int cnt = 0;
    float ls = 0.0f, ss = 0.0f;

    const int ntiles = n / TILE_ELEMS;          // per array
    const int np = (ntiles > b0) ? (ntiles - b0 + G - 1) / G : 0;
    const int nt = np;
    const int total = np + nt;
    const int m2 = 2 * min(np, nt);

    auto issue = [&](int j, int stage) {
        int kind, li;
        if (j < m2) { kind = j & 1; li = j >> 1; }
        else if (np > nt) { kind = 0; li = j - nt; }
        else { kind = 1; li = j - np; }
        int g = b0 + li * G;
        const char* src = kind ? (const char*)targs : (const char*)preds;
        uint32_t mb = smaddr(&mbar[stage]);
        mbar_expect_tx(mb, TILE_BYTES);
        bulk_g2s(smaddr(&buf[stage][0]), src + (size_t)g * TILE_BYTES, TILE_BYTES, mb);
    };

    if (tid == 0) {
        for (int s = 0; s < STAGES && s < total; s++) issue(s, s);
    }

    for (int j = 0; j < total; j++) {
        int st = j % STAGES;
        int parity = (j / STAGES) & 1;
        mbar_wait(smaddr(&mbar[st]), parity);

        int kind, li;
        if (j < m2) { kind = j & 1; li = j >> 1; }
        else if (np > nt) { kind = 0; li = j - nt; }
        else { kind = 1; li = j - np; }
        int g = b0 + li * G;

        if (kind == 0) {
            const float4* fb = reinterpret_cast<const float4*>(&buf[st][0]);
            #pragma unroll
            for (int k = 0; k < 4; k++) {
                float4 p = fb[tid + k * NTHR];
                #pragma unroll
                for (int c = 0; c < 4; c++) {
                    float v = (c == 0) ? p.x : (c == 1) ? p.y : (c == 2) ? p.z : p.w;
                    if (v > Tlo) {
                        float sp = softplus_fast(v);
                        float sg = sigm_fast(v);
                        if (v > Thi) {
                            cnt++; ls += sp; ss += sg;
                        } else {
                            int fb2 = min((int)((v - Tlo) * fscale), FINE_BINS - 1);
                            atomicAdd(&s_cnt[fb2], 1);
                            atomicAdd(&s_loss[fb2], sp);
                            atomicAdd(&s_sig[fb2], sg);
                        }
                    }
                }
            }
            __syncthreads();
        } else {
            const int4* ib = reinterpret_cast<const int4*>(&buf[st][0]);
            int ebase = g * TILE_ELEMS;
            #pragma unroll
            for (int k = 0; k < 4; k++) {
                int v = tid + k * NTHR;
                int4 a = ib[v];
                if (a.x | a.y | a.z | a.w) {
                    int e = ebase + v * 4;
                    if (a.x) { int s = atomicAdd(&s_pcnt, 1); if (s < POS_CAP) s_pos[s] = e + 0; }
                    if (a.y) { int s = atomicAdd(&s_pcnt, 1); if (s < POS_CAP) s_pos[s] = e + 1; }
                    if (a.z) { int s = atomicAdd(&s_pcnt, 1); if (s < POS_CAP) s_pos[s] = e + 2; }
                    if (a.w) { int s = atomicAdd(&s_pcnt, 1); if (s < POS_CAP) s_pos[s] = e + 3; }
                }
            }
            __syncthreads();
            if (s_pcnt > POS_CAP - TILE_ELEMS) {
                int c0 = min(s_pcnt, POS_CAP);
                if (tid == 0) s_base = atomicAdd(&g_pos_n, c0);
                __syncthreads();
                for (int i = tid; i < c0; i += NTHR) {
                    int d = s_base + i;
                    if (d < MAX_POS) g_pos_idx[d] = s_pos[i];
                }
                __syncthreads();
                if (tid == 0) s_pcnt = 0;
                __syncthreads();
            }
        }

        if (tid == 0 && j + STAGES < total) issue(j + STAGES, st);
    }

    // tail elements
    if (b0 == 0) {
        for (int i = ntiles * TILE_ELEMS + tid; i < n; i += NTHR) {
            float v = preds[i];
            if (v > Tlo) {
                float sp = softplus_fast(v);
                float sg = sigm_fast(v);
                if (v > Thi) { cnt++; ls += sp; ss += sg; }
                else {
                    int fb2 = min((int)((v - Tlo) * fscale), FINE_BINS - 1);
                    atomicAdd(&s_cnt[fb2], 1);
                    atomicAdd(&s_loss[fb2], sp);
                    atomicAdd(&s_sig[fb2], sg);
                }
            }
            if (targs[i]) {
                int id = atomicAdd(&g_pos_n, 1);
                if (id < MAX_POS) g_pos_idx[id] = i;
            }
        }
    }

    // final positive flush
    __syncthreads();
    {
        int c0 = min(s_pcnt, POS_CAP);
        if (c0 > 0) {
            if (tid == 0) s_base = atomicAdd(&g_pos_n, c0);
            __syncthreads();
            for (int i = tid; i < c0; i += NTHR) {
                int d = s_base + i;
                if (d < MAX_POS) g_pos_idx[d] = s_pos[i];
            }
        }
    }

    // block reduce above-threshold sums
    for (int off = 16; off > 0; off >>= 1) {
        cnt += __shfl_down_sync(0xffffffffu, cnt, off);
        ls  += __shfl_down_sync(0xffffffffu, ls, off);
        ss  += __shfl_down_sync(0xffffffffu, ss, off);
    }
    int wid = tid >> 5, lid = tid & 31;
    if (lid == 0) { rwc[wid] = cnt; rwl[wid] = ls; rws[wid] = ss; }
    __syncthreads();
    if (tid == 0) {
        int tc = 0; float tl = 0.0f, ts = 0.0f;
        #pragma unroll
        for (int w = 0; w < 8; w++) { tc += rwc[w]; tl += rwl[w]; ts += rws[w]; }
        if (tc) atomicAdd(&g_cnt_above, (unsigned long long)tc);
        atomicAdd(&g_loss_above, (double)tl);
        atomicAdd(&g_sig_above,  (double)ts);
    }
    for (int i = tid; i < FINE_BINS; i += NTHR) {
        int c = s_cnt[i];
        if (c) {
            atomicAdd(&g_fine_cnt[i], c);
            atomicAdd(&g_fine_loss[i], s_loss[i]);
            atomicAdd(&g_fine_sig[i], s_sig[i]);
        }
    }
}

// ---------------------------------------------------------------------------
// k_gather: parallel prefetch of positive values
// ---------------------------------------------------------------------------
__global__ void k_gather(const float* __restrict__ preds) {
    int n_pos = min(g_pos_n, MAX_POS);
    for (int i = blockIdx.x * blockDim.x + threadIdx.x; i < n_pos;
         i += gridDim.x * blockDim.x)
        g_pos_val[i] = preds[g_pos_idx[i]];
}

// ---------------------------------------------------------------------------
// k_final (1 block): exact nhns, positive correction, threshold bin, result
// ---------------------------------------------------------------------------
__global__ void k_final(float* __restrict__ out, int out_size, long long N) {
    __shared__ int       s_cnt[FINE_BINS];
    __shared__ float     s_loss[FINE_BINS];
    __shared__ float     s_sig[FINE_BINS];
    __shared__ long long suf[FINE_BINS];
    __shared__ double    red1[1024], red2[1024];
    __shared__ int       sh_adj_cnt;
    __shared__ double    sh_adj_loss, sh_adj_sig;
    __shared__ int       sh_bstar;
    __shared__ float     sh_result;

    int t = threadIdx.x;
    s_cnt[t]  = g_fine_cnt[t];
    s_loss[t] = g_fine_loss[t];
    s_sig[t]  = g_fine_sig[t];
    if (t == 0) { sh_adj_cnt = 0; sh_adj_loss = 0.0; sh_adj_sig = 0.0; sh_bstar = -1; }
    __syncthreads();

    const float Tlo = g_Tlo, Thi = g_Thi;
    const float fscale = (float)FINE_BINS / (Thi - Tlo);
    int n_pos = min(g_pos_n, MAX_POS);

    double ploss = 0.0, psig = 0.0;
    for (int i = t; i < n_pos; i += blockDim.x) {
        float q  = g_pos_val[i];
        float sp = softplus_acc(q);
        float sg = sigm_fast(q);
        ploss += (double)(sp - q);
        psig  += (double)sg;
        if (q > Thi) {
            float spf = softplus_fast(q);
            atomicAdd(&sh_adj_cnt, 1);
            atomicAdd(&sh_adj_loss, (double)spf);
            atomicAdd(&sh_adj_sig,  (double)sg);
        } else if (q > Tlo) {
            float spf = softplus_fast(q);
            int fb = min((int)((q - Tlo) * fscale), FINE_BINS - 1);
            atomicSub(&s_cnt[fb], 1);
            atomicAdd(&s_loss[fb], -spf);
            atomicAdd(&s_sig[fb],  -sg);
        }
    }
    red1[t] = ploss; red2[t] = psig;
    __syncthreads();
    for (int off = 512; off > 0; off >>= 1) {
        if (t < off) { red1[t] += red1[t + off]; red2[t] += red2[t + off]; }
        __syncthreads();
    }
    double pos_loss = red1[0];
    double pos_sig  = red2[0];
    __syncthreads();

    suf[t] = (long long)s_cnt[t];
    __syncthreads();
    for (int off = 1; off < FINE_BINS; off <<= 1) {
        long long v = (t + off < FINE_BINS) ? suf[t + off] : 0;
        __syncthreads();
        suf[t] += v;
        __syncthreads();
    }

    long long n_posL = (long long)n_pos;
    long long n_neg = N - n_posL;
    long long nhns = (n_posL > 0) ? min(n_posL * 30LL, n_neg)
                                  : (long long)(0.1 * (double)n_neg);
    long long cnt_above = (long long)g_cnt_above - (long long)sh_adj_cnt;

    if (cnt_above + suf[t] >= nhns) atomicMax(&sh_bstar, t);
    __syncthreads();
    int bstar = sh_bstar;

    double fl = 0.0, fs = 0.0;
    if (t > bstar) { fl = (double)s_loss[t]; fs = (double)s_sig[t]; }
    red1[t] = fl; red2[t] = fs;
    __syncthreads();
    for (int off = 512; off > 0; off >>= 1) {
        if (t < off) { red1[t] += red1[t + off]; red2[t] += red2[t + off]; }
        __syncthreads();
    }

    if (t == 0) {
        double neg_loss = g_loss_above - sh_adj_loss + red1[0];
        double neg_sig  = g_sig_above  - sh_adj_sig  + red2[0];
        if (bstar >= 0 && bstar < FINE_BINS && s_cnt[bstar] > 0) {
            long long taken = cnt_above + (suf[bstar] - (long long)s_cnt[bstar]);
            long long r = nhns - taken;
            if (r < 0) r = 0;
            if (r > (long long)s_cnt[bstar]) r = (long long)s_cnt[bstar];
            double frac = (double)r / (double)s_cnt[bstar];
            neg_loss += frac * (double)s_loss[bstar];
            neg_sig  += frac * (double)s_sig[bstar];
        }
        double total_loss = neg_loss + pos_loss;
        double mean_loss  = total_loss / (double)(nhns + n_posL);
        double inter = pos_sig;
        double denom = neg_sig + pos_sig + (double)n_posL;
        double dice  = 1.0 - (2.0 * inter + 1e-10) / (denom + 1e-10);
        sh_result = (float)(dice + mean_loss);
    }
    __syncthreads();
    float r = sh_result;
    for (int i = t; i < out_size; i += blockDim.x) out[i] = r;
}

// ---------------------------------------------------------------------------
extern "C" void kernel_launch(void* const* d_in, const int* in_sizes, int n_in,
                              void* d_out, int out_size) {
    const float* preds = (const float*)d_in[0];
    const int*   targs = (const int*)d_in[1];
    int n = in_sizes[0];

    k_init<<<4, 256>>>();
    k_sample<<<G, NTHR>>>((const float4*)preds, (const int4*)targs, n);
    k_pick<<<1, 1024>>>((long long)n);
    k_stream<<<G, NTHR>>>(preds, targs, n);
    k_gather<<<128, 256>>>(preds);
    k_final<<<1, 1024>>>((float*)d_out, out_size, (long long)n);
}

// round 8
// speedup vs baseline: 2.1787x; 1.3117x over previous
#include <cuda_runtime.h>
#include <math.h>
#include <stdint.h>

#define G 296
#define NTHR 256
#define TILE_ELEMS 4096
#define TILE_BYTES 16384
#define TILE_V4 1024
#define SAMP_BINS 1024
#define FINE_BINS 1024
#define MAX_POS (1 << 20)
#define POSC 2048
#define SAMP_LO (-12.0f)
#define SAMP_W  (24.0f / SAMP_BINS)

static __device__ unsigned           g_bar;
static __device__ int                g_pos_n;
static __device__ int                g_pos_idx[MAX_POS];
static __device__ float              g_pos_val[MAX_POS];
static __device__ int                g_samp_hist[SAMP_BINS];
static __device__ int                g_samp_pos;
static __device__ float              g_Tlo, g_Thi;
static __device__ unsigned long long g_cnt_above;
static __device__ double             g_loss_above, g_sig_above;
static __device__ int                g_fine_cnt[FINE_BINS];
static __device__ float              g_fine_loss[FINE_BINS];
static __device__ float              g_fine_sig[FINE_BINS];

__device__ __forceinline__ float softplus_acc(float x) {
    return fmaxf(x, 0.0f) + log1pf(__expf(-fabsf(x)));
}
__device__ __forceinline__ float softplus_fast(float x) {
    return fmaxf(x, 0.0f) + __logf(1.0f + __expf(-fabsf(x)));
}
__device__ __forceinline__ float sigm_fast(float x) {
    return __fdividef(1.0f, 1.0f + __expf(-x));
}

// ---- TMA helpers ----------------------------------------------------------
__device__ __forceinline__ uint32_t smaddr(const void* p) {
    return (uint32_t)__cvta_generic_to_shared(p);
}
__device__ __forceinline__ void mbar_init(uint32_t a, uint32_t cnt) {
    asm volatile("mbarrier.init.shared.b64 [%0], %1;" :: "r"(a), "r"(cnt) : "memory");
}
__device__ __forceinline__ void mbar_expect_tx(uint32_t a, uint32_t bytes) {
    asm volatile("mbarrier.arrive.expect_tx.shared.b64 _, [%0], %1;" :: "r"(a), "r"(bytes) : "memory");
}
__device__ __forceinline__ void bulk_g2s(uint32_t dst, const void* gsrc, uint32_t bytes, uint32_t mbar) {
    asm volatile(
        "cp.async.bulk.shared::cluster.global.mbarrier::complete_tx::bytes [%0], [%1], %2, [%3];"
        :: "r"(dst), "l"(gsrc), "r"(bytes), "r"(mbar) : "memory");
}
__device__ __forceinline__ void mbar_wait(uint32_t a, uint32_t parity) {
    asm volatile(
        "{\n\t"
        ".reg .pred P1;\n\t"
        "WAIT_LOOP_%=:\n\t"
        "mbarrier.try_wait.parity.acquire.cta.shared::cta.b64 P1, [%0], %1, 0x989680;\n\t"
        "@P1 bra.uni WAIT_DONE_%=;\n\t"
        "bra.uni WAIT_LOOP_%=;\n\t"
        "WAIT_DONE_%=:\n\t"
        "}"
        :: "r"(a), "r"(parity) : "memory");
}

// software grid barrier: all G CTAs resident (2/SM enforced), monotonic count
__device__ __forceinline__ void grid_bar(int tid, unsigned target) {
    __syncthreads();
    if (tid == 0) {
        __threadfence();
        atomicAdd(&g_bar, 1u);
        while (atomicAdd(&g_bar, 0u) < target) __nanosleep(128);
        __threadfence();
    }
    __syncthreads();
}

// ---------------------------------------------------------------------------
__global__ void k_init() {
    int i = threadIdx.x;
    if (i == 0) {
        g_bar = 0u;
        g_pos_n = 0;
        g_samp_pos = 0;
        g_cnt_above = 0ull;
        g_loss_above = 0.0;
        g_sig_above = 0.0;
    }
    if (i < SAMP_BINS) g_samp_hist[i] = 0;
    if (i < FINE_BINS) {
        g_fine_cnt[i] = 0;
        g_fine_loss[i] = 0.0f;
        g_fine_sig[i] = 0.0f;
    }
}

// ---------------------------------------------------------------------------
// THE kernel: sample -> pick -> paired stream -> finale, one launch
// ---------------------------------------------------------------------------
__global__ __launch_bounds__(NTHR, 2) void k_main(
    const float* __restrict__ preds, const int* __restrict__ targs,
    float* __restrict__ out, int out_size, int n)
{
    __shared__ alignas(128) float4 bufP[2][TILE_V4];   // 32KB
    __shared__ alignas(128) int4   bufT[2][TILE_V4];   // 32KB
    __shared__ uint64_t  mbar[2];
    __shared__ int       s_cnt[FINE_BINS];             // also sample hist
    __shared__ float     s_loss[FINE_BINS];
    __shared__ float     s_sig[FINE_BINS];
    __shared__ int       s_pos[POSC];
    __shared__ float     s_posv[POSC];
    __shared__ long long s_scan[NTHR];
    __shared__ double    red1[NTHR], red2[NTHR];
    __shared__ int       s_pcnt, s_base;
    __shared__ int       rwc[8];
    __shared__ float     rwl[8], rws[8];
    __shared__ int       sh_i0, sh_i1;                 // pick: bhi/blo; finale: bstar
    __shared__ long long sh_suf;
    __shared__ double    sh_adj_loss, sh_adj_sig;
    __shared__ int       sh_adj_cnt;
    __shared__ float     sh_result;

    const int tid = threadIdx.x;
    const int b0  = blockIdx.x;
    const int ntiles = n / TILE_ELEMS;
    const int np = (ntiles > b0) ? (ntiles - b0 + G - 1) / G : 0;

    if (tid == 0) {
        s_pcnt = 0;
        mbar_init(smaddr(&mbar[0]), 1);
        mbar_init(smaddr(&mbar[1]), 1);
        asm volatile("fence.proxy.async.shared::cta;" ::: "memory");
    }
    for (int i = tid; i < SAMP_BINS; i += NTHR) s_cnt[i] = 0;   // sample hist
    __syncthreads();

    // prefetch first two tile-PAIRS (preds+targs of same range, one mbar each)
    if (tid == 0) {
        #pragma unroll
        for (int li = 0; li < 2; li++) {
            if (li < np) {
                int g = b0 + li * G;
                uint32_t mb = smaddr(&mbar[li]);
                mbar_expect_tx(mb, 2 * TILE_BYTES);
                bulk_g2s(smaddr(&bufP[li][0]), (const char*)preds + (size_t)g * TILE_BYTES, TILE_BYTES, mb);
                bulk_g2s(smaddr(&bufT[li][0]), (const char*)targs + (size_t)g * TILE_BYTES, TILE_BYTES, mb);
            }
        }
    }

    // ================= phase A: coalesced 1/16 sample =================
    {
        const int n4 = n >> 2;
        const int nseg = n4 / (16 * NTHR);
        const float scale = (float)SAMP_BINS / 24.0f;
        int myp = 0;
        const float4* preds4 = (const float4*)preds;
        const int4*   targs4 = (const int4*)targs;
        for (int s = b0; s < nseg; s += G) {
            int idx4 = s * 16 * NTHR + tid;
            float4 p = __ldcs(&preds4[idx4]);
            int4   t = __ldcs(&targs4[idx4]);
            if (!t.x) { int b = (int)((p.x - SAMP_LO) * scale); b = max(0, min(SAMP_BINS - 1, b)); atomicAdd(&s_cnt[b], 1); } else myp++;
            if (!t.y) { int b = (int)((p.y - SAMP_LO) * scale); b = max(0, min(SAMP_BINS - 1, b)); atomicAdd(&s_cnt[b], 1); } else myp++;
            if (!t.z) { int b = (int)((p.z - SAMP_LO) * scale); b = max(0, min(SAMP_BINS - 1, b)); atomicAdd(&s_cnt[b], 1); } else myp++;
            if (!t.w) { int b = (int)((p.w - SAMP_LO) * scale); b = max(0, min(SAMP_BINS - 1, b)); atomicAdd(&s_cnt[b], 1); } else myp++;
        }
        if (myp) atomicAdd(&g_samp_pos, myp);
        __syncthreads();
        for (int i = tid; i < SAMP_BINS; i += NTHR) {
            int c = s_cnt[i];
            if (c) atomicAdd(&g_samp_hist[i], c);
        }
    }
    grid_bar(tid, G);

    // ================= phase B: pick window (CTA 0) =================
    if (b0 == 0) {
        long long loc0 = __ldcg(&g_samp_hist[4 * tid + 0]);
        long long loc1 = __ldcg(&g_samp_hist[4 * tid + 1]);
        long long loc2 = __ldcg(&g_samp_hist[4 * tid + 2]);
        long long loc3 = __ldcg(&g_samp_hist[4 * tid + 3]);
        if (tid == 0) { sh_i0 = SAMP_BINS; sh_i1 = -1; }
        s_scan[tid] = loc0 + loc1 + loc2 + loc3;
        __syncthreads();
        for (int off = 1; off < NTHR; off <<= 1) {
            long long v = (tid + off < NTHR) ? s_scan[tid + off] : 0;
            __syncthreads();
            s_scan[tid] += v;
            __syncthreads();
        }
        long long below = (tid + 1 < NTHR) ? s_scan[tid + 1] : 0;
        long long suf3 = loc3 + below, suf2 = loc2 + suf3, suf1 = loc1 + suf2, suf0 = loc0 + suf1;

        long long pos_est = 16LL * (long long)__ldcg(&g_samp_pos);
        long long neg_est = (long long)n - pos_est;
        long long nhns = (pos_est > 0) ? min(pos_est * 30LL, neg_est)
                                       : (long long)(0.1 * (double)neg_est);
        long long sufs[4] = {suf0, suf1, suf2, suf3};
        #pragma unroll
        for (int c = 0; c < 4; c++) {
            int bin = 4 * tid + c;
            long long est = 16LL * sufs[c];
            if (est * 100 <= nhns * 65) atomicMin(&sh_i0, bin);
            if (est * 10  >= nhns * 15) atomicMax(&sh_i1, bin);
        }
        __syncthreads();
        if (tid == 0) {
            int bhi = sh_i0, blo = sh_i1;
            if (bhi > SAMP_BINS - 1) bhi = SAMP_BINS - 1;
            if (bhi < 1) bhi = 1;
            if (blo < 0) blo = 0;
            if (blo >= bhi) blo = bhi - 1;
            g_Thi = SAMP_LO + (float)bhi * SAMP_W;
            g_Tlo = SAMP_LO + (float)blo * SAMP_W;
            __threadfence();
        }
    }
    grid_bar(tid, 2 * G);

    // ================= phase C: paired stream =================
    const float Tlo = __ldcg(&g_Tlo), Thi = __ldcg(&g_Thi);
    const float fscale = (float)FINE_BINS / (Thi - Tlo);
    for (int i = tid; i < FINE_BINS; i += NTHR) {
        s_cnt[i] = 0; s_loss[i] = 0.0f; s_sig[i] = 0.0f;
    }
    __syncthreads();

    int cnt = 0;
    float ls = 0.0f, ss = 0.0f;

    for (int li = 0; li < np; li++) {
        int slot = li & 1;
        int parity = (li >> 1) & 1;
        mbar_wait(smaddr(&mbar[slot]), parity);

        // preds tile: sums + fine hist
        #pragma unroll
        for (int k = 0; k < 4; k++) {
            float4 p = bufP[slot][tid + k * NTHR];
            #pragma unroll
            for (int c = 0; c < 4; c++) {
                float v = (c == 0) ? p.x : (c == 1) ? p.y : (c == 2) ? p.z : p.w;
                if (v > Tlo) {
                    float sp = softplus_fast(v);
                    float sg = sigm_fast(v);
                    if (v > Thi) {
                        cnt++; ls += sp; ss += sg;
                    } else {
                        int fb = min((int)((v - Tlo) * fscale), FINE_BINS - 1);
                        atomicAdd(&s_cnt[fb], 1);
                        atomicAdd(&s_loss[fb], sp);
                        atomicAdd(&s_sig[fb], sg);
                    }
                }
            }
        }
        // targs tile: positives, value plucked from resident preds tile
        int ebase = (b0 + li * G) * TILE_ELEMS;
        #pragma unroll
        for (int k = 0; k < 4; k++) {
            int v = tid + k * NTHR;
            int4 a = bufT[slot][v];
            if (a.x | a.y | a.z | a.w) {
                float4 pv = bufP[slot][v];
                int e = ebase + v * 4;
                if (a.x) { int s = atomicAdd(&s_pcnt, 1); if (s < POSC) { s_pos[s] = e + 0; s_posv[s] = pv.x; } else { int d = atomicAdd(&g_pos_n, 1); if (d < MAX_POS) { g_pos_idx[d] = e + 0; g_pos_val[d] = pv.x; } } }
                if (a.y) { int s = atomicAdd(&s_pcnt, 1); if (s < POSC) { s_pos[s] = e + 1; s_posv[s] = pv.y; } else { int d = atomicAdd(&g_pos_n, 1); if (d < MAX_POS) { g_pos_idx[d] = e + 1; g_pos_val[d] = pv.y; } } }
                if (a.z) { int s = atomicAdd(&s_pcnt, 1); if (s < POSC) { s_pos[s] = e + 2; s_posv[s] = pv.z; } else { int d = atomicAdd(&g_pos_n, 1); if (d < MAX_POS) { g_pos_idx[d] = e + 2; g_pos_val[d] = pv.z; } } }
                if (a.w) { int s = atomicAdd(&s_pcnt, 1); if (s < POSC) { s_pos[s] = e + 3; s_posv[s] = pv.w; } else { int d = atomicAdd(&g_pos_n, 1); if (d < MAX_POS) { g_pos_idx[d] = e + 3; g_pos_val[d] = pv.w; } } }
            }
        }
        __syncthreads();   // pair fully consumed

        // flush positives of this tile (usually a handful)
        if (s_pcnt > 0) {
            int c0 = min(s_pcnt, POSC);
            if (tid == 0) s_base = atomicAdd(&g_pos_n, c0);
            __syncthreads();
            for (int i = tid; i < c0; i += NTHR) {
                int d = s_base + i;
                if (d < MAX_POS) { g_pos_idx[d] = s_pos[i]; g_pos_val[d] = s_posv[i]; }
            }
            __syncthreads();
            if (tid == 0) s_pcnt = 0;
        }
        __syncthreads();

        if (tid == 0 && li + 2 < np) {
            int g = b0 + (li + 2) * G;
            uint32_t mb = smaddr(&mbar[slot]);
            mbar_expect_tx(mb, 2 * TILE_BYTES);
            bulk_g2s(smaddr(&bufP[slot][0]), (const char*)preds + (size_t)g * TILE_BYTES, TILE_BYTES, mb);
            bulk_g2s(smaddr(&bufT[slot][0]), (const char*)targs + (size_t)g * TILE_BYTES, TILE_BYTES, mb);
        }
    }

    // tail (n not multiple of TILE_ELEMS): CTA 0
    if (b0 == 0) {
        for (int i = ntiles * TILE_ELEMS + tid; i < n; i += NTHR) {
            float v = preds[i];
            if (v > Tlo) {
                float sp = softplus_fast(v);
                float sg = sigm_fast(v);
                if (v > Thi) { cnt++; ls += sp; ss += sg; }
                else {
                    int fb = min((int)((v - Tlo) * fscale), FINE_BINS - 1);
                    atomicAdd(&s_cnt[fb], 1);
                    atomicAdd(&s_loss[fb], sp);
                    atomicAdd(&s_sig[fb], sg);
                }
            }
            if (targs[i]) {
                int d = atomicAdd(&g_pos_n, 1);
                if (d < MAX_POS) { g_pos_idx[d] = i; g_pos_val[d] = v; }
            }
        }
    }

    // merge above-threshold sums
    for (int off = 16; off > 0; off >>= 1) {
        cnt += __shfl_down_sync(0xffffffffu, cnt, off);
        ls  += __shfl_down_sync(0xffffffffu, ls, off);
        ss  += __shfl_down_sync(0xffffffffu, ss, off);
    }
    int wid = tid >> 5, lid = tid & 31;
    if (lid == 0) { rwc[wid] = cnt; rwl[wid] = ls; rws[wid] = ss; }
    __syncthreads();
    if (tid == 0) {
        int tc = 0; float tl = 0.0f, ts = 0.0f;
        #pragma unroll
        for (int w = 0; w < 8; w++) { tc += rwc[w]; tl += rwl[w]; ts += rws[w]; }
        if (tc) atomicAdd(&g_cnt_above, (unsigned long long)tc);
        atomicAdd(&g_loss_above, (double)tl);
        atomicAdd(&g_sig_above,  (double)ts);
    }
    for (int i = tid; i < FINE_BINS; i += NTHR) {
        int c = s_cnt[i];
        if (c) {
            atomicAdd(&g_fine_cnt[i], c);
            atomicAdd(&g_fine_loss[i], s_loss[i]);
            atomicAdd(&g_fine_sig[i], s_sig[i]);
        }
    }
    grid_bar(tid, 3 * G);

    // ================= phase D: finale (CTA 0, 256 threads) =================
    if (b0 != 0) return;

    // pull corrected fine bins into shared (4 per thread)
    for (int c = 0; c < 4; c++) {
        int bin = 4 * tid + c;
        s_cnt[bin]  = __ldcg(&g_fine_cnt[bin]);
        s_loss[bin] = __ldcg(&g_fine_loss[bin]);
        s_sig[bin]  = __ldcg(&g_fine_sig[bin]);
    }
    if (tid == 0) { sh_adj_cnt = 0; sh_adj_loss = 0.0; sh_adj_sig = 0.0; sh_i0 = -1; }
    __syncthreads();

    int n_pos = min(__ldcg(&g_pos_n), MAX_POS);

    double ploss = 0.0, psig = 0.0;
    for (int i = tid; i < n_pos; i += NTHR) {
        float q  = __ldcg(&g_pos_val[i]);
        float sp = softplus_acc(q);
        float sg = sigm_fast(q);
        ploss += (double)(sp - q);
        psig  += (double)sg;
        if (q > Thi) {
            float spf = softplus_fast(q);   // mirror stream fast math
            atomicAdd(&sh_adj_cnt, 1);
            atomicAdd(&sh_adj_loss, (double)spf);
            atomicAdd(&sh_adj_sig,  (double)sg);
        } else if (q > Tlo) {
            float spf = softplus_fast(q);
            int fb = min((int)((q - Tlo) * fscale), FINE_BINS - 1);
            atomicSub(&s_cnt[fb], 1);
            atomicAdd(&s_loss[fb], -spf);
            atomicAdd(&s_sig[fb],  -sg);
        }
    }
    red1[tid] = ploss; red2[tid] = psig;
    __syncthreads();
    for (int off = NTHR / 2; off > 0; off >>= 1) {
        if (tid < off) { red1[tid] += red1[tid + off]; red2[tid] += red2[tid + off]; }
        __syncthreads();
    }
    double pos_loss = red1[0];
    double pos_sig  = red2[0];
    __syncthreads();

    // suffix scan of corrected counts (4 bins/thread + group scan)
    long long l0 = s_cnt[4 * tid + 0], l1 = s_cnt[4 * tid + 1],
              l2 = s_cnt[4 * tid + 2], l3 = s_cnt[4 * tid + 3];
    s_scan[tid] = l0 + l1 + l2 + l3;
    __syncthreads();
    for (int off = 1; off < NTHR; off <<= 1) {
        long long v = (tid + off < NTHR) ? s_scan[tid + off] : 0;
        __syncthreads();
        s_scan[tid] += v;
        __syncthreads();
    }
    long long below = (tid + 1 < NTHR) ? s_scan[tid + 1] : 0;
    long long suf3 = l3 + below, suf2 = l2 + suf3, suf1 = l1 + suf2, suf0 = l0 + suf1;
    long long sufs[4] = {suf0, suf1, suf2, suf3};

    long long n_posL = (long long)n_pos;
    long long n_neg = (long long)n - n_posL;
    long long nhns = (n_posL > 0) ? min(n_posL * 30LL, n_neg)
                                  : (long long)(0.1 * (double)n_neg);
    long long cnt_above = (long long)g_cnt_above - (long long)sh_adj_cnt;

    #pragma unroll
    for (int c = 0; c < 4; c++) {
        int bin = 4 * tid + c;
        if (cnt_above + sufs[c] >= nhns) atomicMax(&sh_i0, bin);
    }
    __syncthreads();
    int bstar = sh_i0;
    if (bstar >= 0 && (bstar >> 2) == tid) sh_suf = sufs[bstar & 3];
    __syncthreads();

    double fl = 0.0, fs = 0.0;
    #pragma unroll
    for (int c = 0; c < 4; c++) {
        int bin = 4 * tid + c;
        if (bin > bstar) { fl += (double)s_loss[bin]; fs += (double)s_sig[bin]; }
    }
    red1[tid] = fl; red2[tid] = fs;
    __syncthreads();
    for (int off = NTHR / 2; off > 0; off >>= 1) {
        if (tid < off) { red1[tid] += red1[tid + off]; red2[tid] += red2[tid + off]; }
        __syncthreads();
    }

    if (tid == 0) {
        double neg_loss = g_loss_above - sh_adj_loss + red1[0];
        double neg_sig  = g_sig_above  - sh_adj_sig  + red2[0];
        if (bstar >= 0 && bstar < FINE_BINS && s_cnt[bstar] > 0) {
            long long taken = cnt_above + (sh_suf - (long long)s_cnt[bstar]);
            long long r = nhns - taken;
            if (r < 0) r = 0;
            if (r > (long long)s_cnt[bstar]) r = (long long)s_cnt[bstar];
            double frac = (double)r / (double)s_cnt[bstar];
            neg_loss += frac * (double)s_loss[bstar];
            neg_sig  += frac * (double)s_sig[bstar];
        }
        double total_loss = neg_loss + pos_loss;
        double mean_loss  = total_loss / (double)(nhns + n_posL);
        double inter = pos_sig;
        double denom = neg_sig + pos_sig + (double)n_posL;
        double dice  = 1.0 - (2.0 * inter + 1e-10) / (denom + 1e-10);
        sh_result = (float)(dice + mean_loss);
    }
    __syncthreads();
    float r = sh_result;
    for (int i = tid; i < out_size; i += NTHR) out[i] = r;
}

// ---------------------------------------------------------------------------
extern "C" void kernel_launch(void* const* d_in, const int* in_sizes, int n_in,
                              void* d_out, int out_size) {
    const float* preds = (const float*)d_in[0];
    const int*   targs = (const int*)d_in[1];
    int n = in_sizes[0];

    k_init<<<1, 1024>>>();
    k_main<<<G, NTHR>>>(preds, targs, (float*)d_out, out_size, n);
}

// round 9
// speedup vs baseline: 2.1872x; 1.0039x over previous
#include <cuda_runtime.h>
#include <math.h>
#include <stdint.h>

#define G 296
#define NTHR 256
#define STAGES 3
#define TILE_ELEMS 4096
#define TILE_BYTES 16384
#define TILE_V4 1024
#define SAMP_BINS 1024
#define FINE_BINS 1024
#define MAX_POS (1 << 20)
#define SAMP_LO (-12.0f)
#define SAMP_W  (24.0f / SAMP_BINS)

static __device__ unsigned           g_bar;
static __device__ int                g_pos_n;
static __device__ float              g_pos_val[MAX_POS];
static __device__ int                g_samp_hist[SAMP_BINS];
static __device__ int                g_samp_pos;
static __device__ float              g_Tlo, g_Thi;
static __device__ unsigned long long g_cnt_above;
static __device__ double             g_loss_above, g_sig_above;
static __device__ int                g_fine_cnt[FINE_BINS];
static __device__ float              g_fine_loss[FINE_BINS];
static __device__ float              g_fine_sig[FINE_BINS];

__device__ __forceinline__ float softplus_acc(float x) {
    return fmaxf(x, 0.0f) + log1pf(__expf(-fabsf(x)));
}
__device__ __forceinline__ float softplus_fast(float x) {
    return fmaxf(x, 0.0f) + __logf(1.0f + __expf(-fabsf(x)));
}
__device__ __forceinline__ float sigm_fast(float x) {
    return __fdividef(1.0f, 1.0f + __expf(-x));
}

// ---- TMA helpers ----------------------------------------------------------
__device__ __forceinline__ uint32_t smaddr(const void* p) {
    return (uint32_t)__cvta_generic_to_shared(p);
}
__device__ __forceinline__ void mbar_init(uint32_t a, uint32_t cnt) {
    asm volatile("mbarrier.init.shared.b64 [%0], %1;" :: "r"(a), "r"(cnt) : "memory");
}
__device__ __forceinline__ void mbar_expect_tx(uint32_t a, uint32_t bytes) {
    asm volatile("mbarrier.arrive.expect_tx.shared.b64 _, [%0], %1;" :: "r"(a), "r"(bytes) : "memory");
}
__device__ __forceinline__ void bulk_g2s(uint32_t dst, const void* gsrc, uint32_t bytes, uint32_t mbar) {
    asm volatile(
        "cp.async.bulk.shared::cluster.global.mbarrier::complete_tx::bytes [%0], [%1], %2, [%3];"
        :: "r"(dst), "l"(gsrc), "r"(bytes), "r"(mbar) : "memory");
}
__device__ __forceinline__ void mbar_wait(uint32_t a, uint32_t parity) {
    asm volatile(
        "{\n\t"
        ".reg .pred P1;\n\t"
        "WAIT_LOOP_%=:\n\t"
        "mbarrier.try_wait.parity.acquire.cta.shared::cta.b64 P1, [%0], %1, 0x989680;\n\t"
        "@P1 bra.uni WAIT_DONE_%=;\n\t"
        "bra.uni WAIT_LOOP_%=;\n\t"
        "WAIT_DONE_%=:\n\t"
        "}"
        :: "r"(a), "r"(parity) : "memory");
}

// software grid barrier (all G CTAs resident: 2/SM enforced via launch_bounds)
__device__ __forceinline__ void grid_bar(int tid, unsigned target) {
    __syncthreads();
    if (tid == 0) {
        __threadfence();
        atomicAdd(&g_bar, 1u);
        while (atomicAdd(&g_bar, 0u) < target) __nanosleep(128);
        __threadfence();
    }
    __syncthreads();
}

// ---------------------------------------------------------------------------
__global__ void k_init() {
    int i = threadIdx.x;
    if (i == 0) {
        g_bar = 0u;
        g_pos_n = 0;
        g_samp_pos = 0;
        g_cnt_above = 0ull;
        g_loss_above = 0.0;
        g_sig_above = 0.0;
    }
    if (i < SAMP_BINS) g_samp_hist[i] = 0;
    if (i < FINE_BINS) {
        g_fine_cnt[i] = 0;
        g_fine_loss[i] = 0.0f;
        g_fine_sig[i] = 0.0f;
    }
}

// ---------------------------------------------------------------------------
// THE kernel: sample -> pick -> paired 3-stage stream -> finale
// ---------------------------------------------------------------------------
__global__ __launch_bounds__(NTHR, 2) void k_main(
    const float* __restrict__ preds, const int* __restrict__ targs,
    float* __restrict__ out, int out_size, int n)
{
    __shared__ alignas(128) float4 bufP[STAGES][TILE_V4];   // 48KB
    __shared__ alignas(128) int4   bufT[STAGES][TILE_V4];   // 48KB
    __shared__ uint64_t  mbar[STAGES];
    __shared__ int       s_cnt[FINE_BINS];                  // also sample hist
    __shared__ float     s_loss[FINE_BINS];
    __shared__ float     s_sig[FINE_BINS];
    __shared__ long long s_scan[NTHR];
    __shared__ int       rwc[8];
    __shared__ float     rwl[8], rws[8];
    __shared__ double    rwd1[8], rwd2[8];
    __shared__ int       sh_i0, sh_i1;
    __shared__ long long sh_suf;
    __shared__ double    sh_adj_loss, sh_adj_sig;
    __shared__ int       sh_adj_cnt;
    __shared__ float     sh_result;

    const int tid = threadIdx.x;
    const int b0  = blockIdx.x;
    const int ntiles = n / TILE_ELEMS;
    const int np = (ntiles > b0) ? (ntiles - b0 + G - 1) / G : 0;
    const int wid = tid >> 5, lid = tid & 31;

    if (tid == 0) {
        #pragma unroll
        for (int s = 0; s < STAGES; s++) mbar_init(smaddr(&mbar[s]), 1);
        asm volatile("fence.proxy.async.shared::cta;" ::: "memory");
    }
    for (int i = tid; i < SAMP_BINS; i += NTHR) s_cnt[i] = 0;   // sample hist
    __syncthreads();

    // prefetch STAGES tile-pairs (preds+targs same range, one mbar per pair)
    if (tid == 0) {
        #pragma unroll
        for (int li = 0; li < STAGES; li++) {
            if (li < np) {
                int g = b0 + li * G;
                uint32_t mb = smaddr(&mbar[li]);
                mbar_expect_tx(mb, 2 * TILE_BYTES);
                bulk_g2s(smaddr(&bufP[li][0]), (const char*)preds + (size_t)g * TILE_BYTES, TILE_BYTES, mb);
                bulk_g2s(smaddr(&bufT[li][0]), (const char*)targs + (size_t)g * TILE_BYTES, TILE_BYTES, mb);
            }
        }
    }

    // ================= phase A: coalesced 1/16 sample =================
    {
        const int n4 = n >> 2;
        const int nseg = n4 / (16 * NTHR);
        const float scale = (float)SAMP_BINS / 24.0f;
        int myp = 0;
        const float4* preds4 = (const float4*)preds;
        const int4*   targs4 = (const int4*)targs;
        for (int s = b0; s < nseg; s += G) {
            int idx4 = s * 16 * NTHR + tid;
            float4 p = __ldcs(&preds4[idx4]);
            int4   t = __ldcs(&targs4[idx4]);
            if (!t.x) { int b = (int)((p.x - SAMP_LO) * scale); b = max(0, min(SAMP_BINS - 1, b)); atomicAdd(&s_cnt[b], 1); } else myp++;
            if (!t.y) { int b = (int)((p.y - SAMP_LO) * scale); b = max(0, min(SAMP_BINS - 1, b)); atomicAdd(&s_cnt[b], 1); } else myp++;
            if (!t.z) { int b = (int)((p.z - SAMP_LO) * scale); b = max(0, min(SAMP_BINS - 1, b)); atomicAdd(&s_cnt[b], 1); } else myp++;
            if (!t.w) { int b = (int)((p.w - SAMP_LO) * scale); b = max(0, min(SAMP_BINS - 1, b)); atomicAdd(&s_cnt[b], 1); } else myp++;
        }
        if (myp) atomicAdd(&g_samp_pos, myp);
        __syncthreads();
        for (int i = tid; i < SAMP_BINS; i += NTHR) {
            int c = s_cnt[i];
            if (c) atomicAdd(&g_samp_hist[i], c);
        }
    }
    grid_bar(tid, G);

    // ================= phase B: pick window (CTA 0) =================
    if (b0 == 0) {
        long long loc0 = __ldcg(&g_samp_hist[4 * tid + 0]);
        long long loc1 = __ldcg(&g_samp_hist[4 * tid + 1]);
        long long loc2 = __ldcg(&g_samp_hist[4 * tid + 2]);
        long long loc3 = __ldcg(&g_samp_hist[4 * tid + 3]);
        if (tid == 0) { sh_i0 = SAMP_BINS; sh_i1 = -1; }
        s_scan[tid] = loc0 + loc1 + loc2 + loc3;
        __syncthreads();
        for (int off = 1; off < NTHR; off <<= 1) {
            long long v = (tid + off < NTHR) ? s_scan[tid + off] : 0;
            __syncthreads();
            s_scan[tid] += v;
            __syncthreads();
        }
        long long below = (tid + 1 < NTHR) ? s_scan[tid + 1] : 0;
        long long suf3 = loc3 + below, suf2 = loc2 + suf3, suf1 = loc1 + suf2, suf0 = loc0 + suf1;

        long long pos_est = 16LL * (long long)__ldcg(&g_samp_pos);
        long long neg_est = (long long)n - pos_est;
        long long nhns = (pos_est > 0) ? min(pos_est * 30LL, neg_est)
                                       : (long long)(0.1 * (double)neg_est);
        long long sufs[4] = {suf0, suf1, suf2, suf3};
        #pragma unroll
        for (int c = 0; c < 4; c++) {
            int bin = 4 * tid + c;
            long long est = 16LL * sufs[c];
            if (est * 100 <= nhns * 65) atomicMin(&sh_i0, bin);
            if (est * 10  >= nhns * 15) atomicMax(&sh_i1, bin);
        }
        __syncthreads();
        if (tid == 0) {
            int bhi = sh_i0, blo = sh_i1;
            if (bhi > SAMP_BINS - 1) bhi = SAMP_BINS - 1;
            if (bhi < 1) bhi = 1;
            if (blo < 0) blo = 0;
            if (blo >= bhi) blo = bhi - 1;
            g_Thi = SAMP_LO + (float)bhi * SAMP_W;
            g_Tlo = SAMP_LO + (float)blo * SAMP_W;
            __threadfence();
        }
    }
    grid_bar(tid, 2 * G);

    // ================= phase C: paired stream (3-stage ring) =================
    const float Tlo = __ldcg(&g_Tlo), Thi = __ldcg(&g_Thi);
    const float fscale = (float)FINE_BINS / (Thi - Tlo);
    for (int i = tid; i < FINE_BINS; i += NTHR) {
        s_cnt[i] = 0; s_loss[i] = 0.0f; s_sig[i] = 0.0f;
    }
    __syncthreads();

    int cnt = 0;
    float ls = 0.0f, ss = 0.0f;

    for (int li = 0; li < np; li++) {
        int slot = li % STAGES;
        int parity = (li / STAGES) & 1;
        mbar_wait(smaddr(&mbar[slot]), parity);

        // preds tile: above-threshold sums + fine hist
        #pragma unroll
        for (int k = 0; k < 4; k++) {
            float4 p = bufP[slot][tid + k * NTHR];
            #pragma unroll
            for (int c = 0; c < 4; c++) {
                float v = (c == 0) ? p.x : (c == 1) ? p.y : (c == 2) ? p.z : p.w;
                if (v > Tlo) {
                    float sp = softplus_fast(v);
                    float sg = sigm_fast(v);
                    if (v > Thi) {
                        cnt++; ls += sp; ss += sg;
                    } else {
                        int fb = min((int)((v - Tlo) * fscale), FINE_BINS - 1);
                        atomicAdd(&s_cnt[fb], 1);
                        atomicAdd(&s_loss[fb], sp);
                        atomicAdd(&s_sig[fb], sg);
                    }
                }
            }
        }
        // targs tile: positives written straight to global (values from smem)
        #pragma unroll
        for (int k = 0; k < 4; k++) {
            int v = tid + k * NTHR;
            int4 a = bufT[slot][v];
            if (a.x | a.y | a.z | a.w) {
                float4 pv = bufP[slot][v];
                if (a.x) { int d = atomicAdd(&g_pos_n, 1); if (d < MAX_POS) g_pos_val[d] = pv.x; }
                if (a.y) { int d = atomicAdd(&g_pos_n, 1); if (d < MAX_POS) g_pos_val[d] = pv.y; }
                if (a.z) { int d = atomicAdd(&g_pos_n, 1); if (d < MAX_POS) g_pos_val[d] = pv.z; }
                if (a.w) { int d = atomicAdd(&g_pos_n, 1); if (d < MAX_POS) g_pos_val[d] = pv.w; }
            }
        }
        __syncthreads();   // pair fully consumed

        if (tid == 0 && li + STAGES < np) {
            int g = b0 + (li + STAGES) * G;
            uint32_t mb = smaddr(&mbar[slot]);
            mbar_expect_tx(mb, 2 * TILE_BYTES);
            bulk_g2s(smaddr(&bufP[slot][0]), (const char*)preds + (size_t)g * TILE_BYTES, TILE_BYTES, mb);
            bulk_g2s(smaddr(&bufT[slot][0]), (const char*)targs + (size_t)g * TILE_BYTES, TILE_BYTES, mb);
        }
    }

    // tail elements (n not multiple of TILE_ELEMS): CTA 0
    if (b0 == 0) {
        for (int i = ntiles * TILE_ELEMS + tid; i < n; i += NTHR) {
            float v = preds[i];
            if (v > Tlo) {
                float sp = softplus_fast(v);
                float sg = sigm_fast(v);
                if (v > Thi) { cnt++; ls += sp; ss += sg; }
                else {
                    int fb = min((int)((v - Tlo) * fscale), FINE_BINS - 1);
                    atomicAdd(&s_cnt[fb], 1);
                    atomicAdd(&s_loss[fb], sp);
                    atomicAdd(&s_sig[fb], sg);
                }
            }
            if (targs[i]) {
                int d = atomicAdd(&g_pos_n, 1);
                if (d < MAX_POS) g_pos_val[d] = v;
            }
        }
    }

    // merge above-threshold sums
    for (int off = 16; off > 0; off >>= 1) {
        cnt += __shfl_down_sync(0xffffffffu, cnt, off);
        ls  += __shfl_down_sync(0xffffffffu, ls, off);
        ss  += __shfl_down_sync(0xffffffffu, ss, off);
    }
    if (lid == 0) { rwc[wid] = cnt; rwl[wid] = ls; rws[wid] = ss; }
    __syncthreads();
    if (tid == 0) {
        int tc = 0; float tl = 0.0f, ts = 0.0f;
        #pragma unroll
        for (int w = 0; w < 8; w++) { tc += rwc[w]; tl += rwl[w]; ts += rws[w]; }
        if (tc) atomicAdd(&g_cnt_above, (unsigned long long)tc);
        atomicAdd(&g_loss_above, (double)tl);
        atomicAdd(&g_sig_above,  (double)ts);
    }
    for (int i = tid; i < FINE_BINS; i += NTHR) {
        int c = s_cnt[i];
        if (c) {
            atomicAdd(&g_fine_cnt[i], c);
            atomicAdd(&g_fine_loss[i], s_loss[i]);
            atomicAdd(&g_fine_sig[i], s_sig[i]);
        }
    }
    grid_bar(tid, 3 * G);

    // ================= phase D: finale (CTA 0) =================
    if (b0 != 0) return;

    for (int c = 0; c < 4; c++) {
        int bin = 4 * tid + c;
        s_cnt[bin]  = __ldcg(&g_fine_cnt[bin]);
        s_loss[bin] = __ldcg(&g_fine_loss[bin]);
        s_sig[bin]  = __ldcg(&g_fine_sig[bin]);
    }
    if (tid == 0) { sh_adj_cnt = 0; sh_adj_loss = 0.0; sh_adj_sig = 0.0; sh_i0 = -1; }
    __syncthreads();

    int n_pos = min(__ldcg(&g_pos_n), MAX_POS);

    double ploss = 0.0, psig = 0.0;
    for (int i = tid; i < n_pos; i += NTHR) {
        float q  = __ldcg(&g_pos_val[i]);
        float sp = softplus_acc(q);
        float sg = sigm_fast(q);
        ploss += (double)(sp - q);
        psig  += (double)sg;
        if (q > Thi) {
            float spf = softplus_fast(q);   // mirror stream fast math
            atomicAdd(&sh_adj_cnt, 1);
            atomicAdd(&sh_adj_loss, (double)spf);
            atomicAdd(&sh_adj_sig,  (double)sg);
        } else if (q > Tlo) {
            float spf = softplus_fast(q);
            int fb = min((int)((q - Tlo) * fscale), FINE_BINS - 1);
            atomicSub(&s_cnt[fb], 1);
            atomicAdd(&s_loss[fb], -spf);
            atomicAdd(&s_sig[fb],  -sg);
        }
    }
    // warp-shuffle double reduction of (ploss, psig)
    for (int off = 16; off > 0; off >>= 1) {
        ploss += __shfl_down_sync(0xffffffffu, ploss, off);
        psig  += __shfl_down_sync(0xffffffffu, psig, off);
    }
    if (lid == 0) { rwd1[wid] = ploss; rwd2[wid] = psig; }
    __syncthreads();
    double pos_loss = 0.0, pos_sig = 0.0;
    if (tid == 0) {
        #pragma unroll
        for (int w = 0; w < 8; w++) { pos_loss += rwd1[w]; pos_sig += rwd2[w]; }
        rwd1[0] = pos_loss; rwd2[0] = pos_sig;
    }
    __syncthreads();
    pos_loss = rwd1[0]; pos_sig = rwd2[0];

    // suffix scan of corrected counts
    long long l0 = s_cnt[4 * tid + 0], l1 = s_cnt[4 * tid + 1],
              l2 = s_cnt[4 * tid + 2], l3 = s_cnt[4 * tid + 3];
    s_scan[tid] = l0 + l1 + l2 + l3;
    __syncthreads();
    for (int off = 1; off < NTHR; off <<= 1) {
        long long v = (tid + off < NTHR) ? s_scan[tid + off] : 0;
        __syncthreads();
        s_scan[tid] += v;
        __syncthreads();
    }
    long long below = (tid + 1 < NTHR) ? s_scan[tid + 1] : 0;
    long long suf3 = l3 + below, suf2 = l2 + suf3, suf1 = l1 + suf2, suf0 = l0 + suf1;
    long long sufs[4] = {suf0, suf1, suf2, suf3};

    long long n_posL = (long long)n_pos;
    long long n_neg = (long long)n - n_posL;
    long long nhns = (n_posL > 0) ? min(n_posL * 30LL, n_neg)
                                  : (long long)(0.1 * (double)n_neg);
    long long cnt_above = (long long)g_cnt_above - (long long)sh_adj_cnt;

    #pragma unroll
    for (int c = 0; c < 4; c++) {
        int bin = 4 * tid + c;
        if (cnt_above + sufs[c] >= nhns) atomicMax(&sh_i0, bin);
    }
    __syncthreads();
    int bstar = sh_i0;
    if (bstar >= 0 && (bstar >> 2) == tid) sh_suf = sufs[bstar & 3];
    __syncthreads();

    double fl = 0.0, fs = 0.0;
    #pragma unroll
    for (int c = 0; c < 4; c++) {
        int bin = 4 * tid + c;
        if (bin > bstar) { fl += (double)s_loss[bin]; fs += (double)s_sig[bin]; }
    }
    for (int off = 16; off > 0; off >>= 1) {
        fl += __shfl_down_sync(0xffffffffu, fl, off);
        fs += __shfl_down_sync(0xffffffffu, fs, off);
    }
    if (lid == 0) { rwd1[wid] = fl; rwd2[wid] = fs; }
    __syncthreads();

    if (tid == 0) {
        double sfl = 0.0, sfs = 0.0;
        #pragma unroll
        for (int w = 0; w < 8; w++) { sfl += rwd1[w]; sfs += rwd2[w]; }
        double neg_loss = g_loss_above - sh_adj_loss + sfl;
        double neg_sig  = g_sig_above  - sh_adj_sig  + sfs;
        if (bstar >= 0 && bstar < FINE_BINS && s_cnt[bstar] > 0) {
            long long taken = cnt_above + (sh_suf - (long long)s_cnt[bstar]);
            long long r = nhns - taken;
            if (r < 0) r = 0;
            if (r > (long long)s_cnt[bstar]) r = (long long)s_cnt[bstar];
            double frac = (double)r / (double)s_cnt[bstar];
            neg_loss += frac * (double)s_loss[bstar];
            neg_sig  += frac * (double)s_sig[bstar];
        }
        double total_loss = neg_loss + pos_loss;
        double mean_loss  = total_loss / (double)(nhns + n_posL);
        double inter = pos_sig;
        double denom = neg_sig + pos_sig + (double)n_posL;
        double dice  = 1.0 - (2.0 * inter + 1e-10) / (denom + 1e-10);
        sh_result = (float)(dice + mean_loss);
    }
    __syncthreads();
    float r = sh_result;
    for (int i = tid; i < out_size; i += NTHR) out[i] = r;
}

// ---------------------------------------------------------------------------
extern "C" void kernel_launch(void* const* d_in, const int* in_sizes, int n_in,
                              void* d_out, int out_size) {
    const float* preds = (const float*)d_in[0];
    const int*   targs = (const int*)d_in[1];
    int n = in_sizes[0];

    k_init<<<1, 1024>>>();
    k_main<<<G, NTHR>>>(preds, targs, (float*)d_out, out_size, n);
}

// round 10
// speedup vs baseline: 2.2935x; 1.0486x over previous
#include <cuda_runtime.h>
#include <math.h>
#include <stdint.h>

#define G 296
#define NTHR 256
#define STAGES 3
#define TILE_ELEMS 4096
#define TILE_BYTES 16384
#define TILE_V4 1024
#define SAMP_BINS 1024
#define FINE_BINS 1024
#define MAX_POS (1 << 20)
#define SAMP_LO (-12.0f)
#define SAMP_W  (24.0f / SAMP_BINS)
#define LBATCH 4            // float4/int4 pairs per thread per iter (LDG path)

static __device__ unsigned           g_bar;
static __device__ int                g_pos_n;
static __device__ float              g_pos_val[MAX_POS];
static __device__ int                g_samp_hist[SAMP_BINS];
static __device__ int                g_samp_pos;
static __device__ float              g_Tlo, g_Thi;
static __device__ unsigned long long g_cnt_above;
static __device__ double             g_loss_above, g_sig_above;
static __device__ int                g_fine_cnt[FINE_BINS];
static __device__ float              g_fine_loss[FINE_BINS];
static __device__ float              g_fine_sig[FINE_BINS];

__device__ __forceinline__ float softplus_acc(float x) {
    return fmaxf(x, 0.0f) + log1pf(__expf(-fabsf(x)));
}
// shared-exp fast path: 3 MUFU. Used identically in stream AND finale mirror.
__device__ __forceinline__ void fast_sp_sg(float v, float& sp, float& sg) {
    float e = __expf(-fabsf(v));
    float l = __logf(1.0f + e);
    float r = __fdividef(1.0f, 1.0f + e);
    sp = fmaxf(v, 0.0f) + l;
    sg = (v >= 0.0f) ? r : 1.0f - r;
}
__device__ __forceinline__ float sigm_fast(float x) {
    return __fdividef(1.0f, 1.0f + __expf(-x));
}

// ---- TMA helpers ----------------------------------------------------------
__device__ __forceinline__ uint32_t smaddr(const void* p) {
    return (uint32_t)__cvta_generic_to_shared(p);
}
__device__ __forceinline__ void mbar_init(uint32_t a, uint32_t cnt) {
    asm volatile("mbarrier.init.shared.b64 [%0], %1;" :: "r"(a), "r"(cnt) : "memory");
}
__device__ __forceinline__ void mbar_expect_tx(uint32_t a, uint32_t bytes) {
    asm volatile("mbarrier.arrive.expect_tx.shared.b64 _, [%0], %1;" :: "r"(a), "r"(bytes) : "memory");
}
__device__ __forceinline__ void bulk_g2s(uint32_t dst, const void* gsrc, uint32_t bytes, uint32_t mbar) {
    asm volatile(
        "cp.async.bulk.shared::cluster.global.mbarrier::complete_tx::bytes [%0], [%1], %2, [%3];"
        :: "r"(dst), "l"(gsrc), "r"(bytes), "r"(mbar) : "memory");
}
__device__ __forceinline__ void mbar_wait(uint32_t a, uint32_t parity) {
    asm volatile(
        "{\n\t"
        ".reg .pred P1;\n\t"
        "WAIT_LOOP_%=:\n\t"
        "mbarrier.try_wait.parity.acquire.cta.shared::cta.b64 P1, [%0], %1, 0x989680;\n\t"
        "@P1 bra.uni WAIT_DONE_%=;\n\t"
        "bra.uni WAIT_LOOP_%=;\n\t"
        "WAIT_DONE_%=:\n\t"
        "}"
        :: "r"(a), "r"(parity) : "memory");
}

__device__ __forceinline__ void grid_bar(int tid, unsigned target) {
    __syncthreads();
    if (tid == 0) {
        __threadfence();
        atomicAdd(&g_bar, 1u);
        while (atomicAdd(&g_bar, 0u) < target) __nanosleep(128);
        __threadfence();
    }
    __syncthreads();
}

// ---------------------------------------------------------------------------
__global__ void k_init() {
    int i = threadIdx.x;
    if (i == 0) {
        g_bar = 0u;
        g_pos_n = 0;
        g_samp_pos = 0;
        g_cnt_above = 0ull;
        g_loss_above = 0.0;
        g_sig_above = 0.0;
    }
    if (i < SAMP_BINS) g_samp_hist[i] = 0;
    if (i < FINE_BINS) {
        g_fine_cnt[i] = 0;
        g_fine_loss[i] = 0.0f;
        g_fine_sig[i] = 0.0f;
    }
}

// ---------------------------------------------------------------------------
// THE kernel: sample -> pick -> dual-path stream (TMA + LDG) -> finale
// ---------------------------------------------------------------------------
__global__ __launch_bounds__(NTHR, 2) void k_main(
    const float* __restrict__ preds, const int* __restrict__ targs,
    float* __restrict__ out, int out_size, int n)
{
    __shared__ alignas(128) float4 bufP[STAGES][TILE_V4];   // 48KB
    __shared__ alignas(128) int4   bufT[STAGES][TILE_V4];   // 48KB
    __shared__ uint64_t  mbar[STAGES];
    __shared__ int       s_cnt[FINE_BINS];                  // also sample hist
    __shared__ float     s_loss[FINE_BINS];
    __shared__ float     s_sig[FINE_BINS];
    __shared__ long long s_scan[NTHR];
    __shared__ int       rwc[8];
    __shared__ float     rwl[8], rws[8];
    __shared__ double    rwd1[8], rwd2[8];
    __shared__ int       sh_i0, sh_i1;
    __shared__ long long sh_suf;
    __shared__ double    sh_adj_loss, sh_adj_sig;
    __shared__ int       sh_adj_cnt;
    __shared__ float     sh_result;

    const int tid = threadIdx.x;
    const int b0  = blockIdx.x;
    const int wid = tid >> 5, lid = tid & 31;

    const int ntiles = n / TILE_ELEMS;
    const int t_tiles = ntiles >> 1;                  // TMA region: first half
    const int np = (t_tiles > b0) ? (t_tiles - b0 + G - 1) / G : 0;

    const int n4 = n >> 2;
    const int l4base = t_tiles * (TILE_ELEMS / 4);    // LDG region start (v4)
    const int lspan = G * NTHR;                       // v4 per j-step chip-wide
    const int lchunk = lspan * LBATCH;                // v4 per iteration chip-wide
    const int ldg_v4 = n4 - l4base;
    const int liters = (ldg_v4 + lchunk - 1) / lchunk;
    const int IT = (np > liters) ? np : liters;

    if (tid == 0) {
        #pragma unroll
        for (int s = 0; s < STAGES; s++) mbar_init(smaddr(&mbar[s]), 1);
        asm volatile("fence.proxy.async.shared::cta;" ::: "memory");
    }
    for (int i = tid; i < SAMP_BINS; i += NTHR) s_cnt[i] = 0;   // sample hist
    __syncthreads();

    // prefetch STAGES tile-pairs of the TMA region
    if (tid == 0) {
        #pragma unroll
        for (int li = 0; li < STAGES; li++) {
            if (li < np) {
                int g = b0 + li * G;
                uint32_t mb = smaddr(&mbar[li]);
                mbar_expect_tx(mb, 2 * TILE_BYTES);
                bulk_g2s(smaddr(&bufP[li][0]), (const char*)preds + (size_t)g * TILE_BYTES, TILE_BYTES, mb);
                bulk_g2s(smaddr(&bufT[li][0]), (const char*)targs + (size_t)g * TILE_BYTES, TILE_BYTES, mb);
            }
        }
    }

    // ================= phase A: coalesced 1/32 sample =================
    {
        const int nseg = n4 / (32 * NTHR);
        const float scale = (float)SAMP_BINS / 24.0f;
        int myp = 0;
        const float4* preds4 = (const float4*)preds;
        const int4*   targs4 = (const int4*)targs;
        for (int s = b0; s < nseg; s += G) {
            int idx4 = s * 32 * NTHR + tid;
            float4 p = __ldcs(&preds4[idx4]);
            int4   t = __ldcs(&targs4[idx4]);
            if (!t.x) { int b = (int)((p.x - SAMP_LO) * scale); b = max(0, min(SAMP_BINS - 1, b)); atomicAdd(&s_cnt[b], 1); } else myp++;
            if (!t.y) { int b = (int)((p.y - SAMP_LO) * scale); b = max(0, min(SAMP_BINS - 1, b)); atomicAdd(&s_cnt[b], 1); } else myp++;
            if (!t.z) { int b = (int)((p.z - SAMP_LO) * scale); b = max(0, min(SAMP_BINS - 1, b)); atomicAdd(&s_cnt[b], 1); } else myp++;
            if (!t.w) { int b = (int)((p.w - SAMP_LO) * scale); b = max(0, min(SAMP_BINS - 1, b)); atomicAdd(&s_cnt[b], 1); } else myp++;
        }
        if (myp) atomicAdd(&g_samp_pos, myp);
        __syncthreads();
        for (int i = tid; i < SAMP_BINS; i += NTHR) {
            int c = s_cnt[i];
            if (c) atomicAdd(&g_samp_hist[i], c);
        }
    }
    grid_bar(tid, G);

    // ================= phase B: pick window (CTA 0) =================
    if (b0 == 0) {
        long long loc0 = __ldcg(&g_samp_hist[4 * tid + 0]);
        long long loc1 = __ldcg(&g_samp_hist[4 * tid + 1]);
        long long loc2 = __ldcg(&g_samp_hist[4 * tid + 2]);
        long long loc3 = __ldcg(&g_samp_hist[4 * tid + 3]);
        if (tid == 0) { sh_i0 = SAMP_BINS; sh_i1 = -1; }
        s_scan[tid] = loc0 + loc1 + loc2 + loc3;
        __syncthreads();
        for (int off = 1; off < NTHR; off <<= 1) {
            long long v = (tid + off < NTHR) ? s_scan[tid + off] : 0;
            __syncthreads();
            s_scan[tid] += v;
            __syncthreads();
        }
        long long below = (tid + 1 < NTHR) ? s_scan[tid + 1] : 0;
        long long suf3 = loc3 + below, suf2 = loc2 + suf3, suf1 = loc1 + suf2, suf0 = loc0 + suf1;

        long long pos_est = 32LL * (long long)__ldcg(&g_samp_pos);
        long long neg_est = (long long)n - pos_est;
        long long nhns = (pos_est > 0) ? min(pos_est * 30LL, neg_est)
                                       : (long long)(0.1 * (double)neg_est);
        long long sufs[4] = {suf0, suf1, suf2, suf3};
        #pragma unroll
        for (int c = 0; c < 4; c++) {
            int bin = 4 * tid + c;
            long long est = 32LL * sufs[c];
            if (est * 100 <= nhns * 65) atomicMin(&sh_i0, bin);
            if (est * 10  >= nhns * 15) atomicMax(&sh_i1, bin);
        }
        __syncthreads();
        if (tid == 0) {
            int bhi = sh_i0, blo = sh_i1;
            if (bhi > SAMP_BINS - 1) bhi = SAMP_BINS - 1;
            if (bhi < 1) bhi = 1;
            if (blo < 0) blo = 0;
            if (blo >= bhi) blo = bhi - 1;
            g_Thi = SAMP_LO + (float)bhi * SAMP_W;
            g_Tlo = SAMP_LO + (float)blo * SAMP_W;
            __threadfence();
        }
    }
    grid_bar(tid, 2 * G);

    // ================= phase C: dual-path stream =================
    const float Tlo = __ldcg(&g_Tlo), Thi = __ldcg(&g_Thi);
    const float fscale = (float)FINE_BINS / (Thi - Tlo);
    for (int i = tid; i < FINE_BINS; i += NTHR) {
        s_cnt[i] = 0; s_loss[i] = 0.0f; s_sig[i] = 0.0f;
    }
    __syncthreads();

    int cnt = 0;
    float ls = 0.0f, ss = 0.0f;
    const float4* preds4 = (const float4*)preds;
    const int4*   targs4 = (const int4*)targs;

    auto proc_val = [&](float v) {
        if (v > Tlo) {
            float sp, sg;
            fast_sp_sg(v, sp, sg);
            if (v > Thi) {
                cnt++; ls += sp; ss += sg;
            } else {
                int fb = min((int)((v - Tlo) * fscale), FINE_BINS - 1);
                atomicAdd(&s_cnt[fb], 1);
                atomicAdd(&s_loss[fb], sp);
                atomicAdd(&s_sig[fb], sg);
            }
        }
    };
    auto proc_pos4 = [&](int4 a, float4 pv) {
        if (a.x | a.y | a.z | a.w) {
            if (a.x) { int d = atomicAdd(&g_pos_n, 1); if (d < MAX_POS) g_pos_val[d] = pv.x; }
            if (a.y) { int d = atomicAdd(&g_pos_n, 1); if (d < MAX_POS) g_pos_val[d] = pv.y; }
            if (a.z) { int d = atomicAdd(&g_pos_n, 1); if (d < MAX_POS) g_pos_val[d] = pv.z; }
            if (a.w) { int d = atomicAdd(&g_pos_n, 1); if (d < MAX_POS) g_pos_val[d] = pv.w; }
        }
    };

    for (int it = 0; it < IT; it++) {
        // ---- fire the LDG batch for this iteration (flies during TMA work) ----
        float4 lp[LBATCH];
        int4   lt[LBATCH];
        bool lact = (it < liters);
        int base4 = l4base + it * lchunk + b0 * NTHR + tid;
        #pragma unroll
        for (int j = 0; j < LBATCH; j++) {
            int idx4 = base4 + j * lspan;
            if (lact && idx4 < n4) {
                lp[j] = __ldcs(&preds4[idx4]);
                lt[j] = __ldcs(&targs4[idx4]);
            } else {
                lp[j] = make_float4(-1e30f, -1e30f, -1e30f, -1e30f);
                lt[j] = make_int4(0, 0, 0, 0);
            }
        }

        // ---- TMA pair for this iteration ----
        if (it < np) {
            int slot = it % STAGES;
            int parity = (it / STAGES) & 1;
            mbar_wait(smaddr(&mbar[slot]), parity);

            #pragma unroll
            for (int k = 0; k < 4; k++) {
                float4 p = bufP[slot][tid + k * NTHR];
                proc_val(p.x); proc_val(p.y); proc_val(p.z); proc_val(p.w);
            }
            #pragma unroll
            for (int k = 0; k < 4; k++) {
                int v = tid + k * NTHR;
                int4 a = bufT[slot][v];
                if (a.x | a.y | a.z | a.w) proc_pos4(a, bufP[slot][v]);
            }
            __syncthreads();   // pair fully consumed

            if (tid == 0 && it + STAGES < np) {
                int g = b0 + (it + STAGES) * G;
                uint32_t mb = smaddr(&mbar[slot]);
                mbar_expect_tx(mb, 2 * TILE_BYTES);
                bulk_g2s(smaddr(&bufP[slot][0]), (const char*)preds + (size_t)g * TILE_BYTES, TILE_BYTES, mb);
                bulk_g2s(smaddr(&bufT[slot][0]), (const char*)targs + (size_t)g * TILE_BYTES, TILE_BYTES, mb);
            }
        }

        // ---- process the LDG batch (next TMA already in flight) ----
        #pragma unroll
        for (int j = 0; j < LBATCH; j++) {
            float4 p = lp[j];
            proc_val(p.x); proc_val(p.y); proc_val(p.z); proc_val(p.w);
            proc_pos4(lt[j], p);
        }
    }

    // tail elements (n not multiple of TILE_ELEMS): CTA 0
    if (b0 == 0) {
        for (int i = ntiles * TILE_ELEMS + tid; i < n; i += NTHR) {
            float v = preds[i];
            proc_val(v);
            if (targs[i]) {
                int d = atomicAdd(&g_pos_n, 1);
                if (d < MAX_POS) g_pos_val[d] = v;
            }
        }
    }

    // merge above-threshold sums
    for (int off = 16; off > 0; off >>= 1) {
        cnt += __shfl_down_sync(0xffffffffu, cnt, off);
        ls  += __shfl_down_sync(0xffffffffu, ls, off);
        ss  += __shfl_down_sync(0xffffffffu, ss, off);
    }
    if (lid == 0) { rwc[wid] = cnt; rwl[wid] = ls; rws[wid] = ss; }
    __syncthreads();
    if (tid == 0) {
        int tc = 0; float tl = 0.0f, ts = 0.0f;
        #pragma unroll
        for (int w = 0; w < 8; w++) { tc += rwc[w]; tl += rwl[w]; ts += rws[w]; }
        if (tc) atomicAdd(&g_cnt_above, (unsigned long long)tc);
        atomicAdd(&g_loss_above, (double)tl);
        atomicAdd(&g_sig_above,  (double)ts);
    }
    for (int i = tid; i < FINE_BINS; i += NTHR) {
        int c = s_cnt[i];
        if (c) {
            atomicAdd(&g_fine_cnt[i], c);
            atomicAdd(&g_fine_loss[i], s_loss[i]);
            atomicAdd(&g_fine_sig[i], s_sig[i]);
        }
    }
    grid_bar(tid, 3 * G);

    // ================= phase D: finale (CTA 0) =================
    if (b0 != 0) return;

    for (int c = 0; c < 4; c++) {
        int bin = 4 * tid + c;
        s_cnt[bin]  = __ldcg(&g_fine_cnt[bin]);
        s_loss[bin] = __ldcg(&g_fine_loss[bin]);
        s_sig[bin]  = __ldcg(&g_fine_sig[bin]);
    }
    if (tid == 0) { sh_adj_cnt = 0; sh_adj_loss = 0.0; sh_adj_sig = 0.0; sh_i0 = -1; }
    __syncthreads();

    int n_pos = min(__ldcg(&g_pos_n), MAX_POS);

    double ploss = 0.0, psig = 0.0;
    for (int i = tid; i < n_pos; i += NTHR) {
        float q  = __ldcg(&g_pos_val[i]);
        float sp_a = softplus_acc(q);
        float sg_a = sigm_fast(q);
        ploss += (double)(sp_a - q);
        psig  += (double)sg_a;
        if (q > Tlo) {
            float spf, sgf;
            fast_sp_sg(q, spf, sgf);     // EXACT mirror of stream fast path
            if (q > Thi) {
                atomicAdd(&sh_adj_cnt, 1);
                atomicAdd(&sh_adj_loss, (double)spf);
                atomicAdd(&sh_adj_sig,  (double)sgf);
            } else {
                int fb = min((int)((q - Tlo) * fscale), FINE_BINS - 1);
                atomicSub(&s_cnt[fb], 1);
                atomicAdd(&s_loss[fb], -spf);
                atomicAdd(&s_sig[fb],  -sgf);
            }
        }
    }
    for (int off = 16; off > 0; off >>= 1) {
        ploss += __shfl_down_sync(0xffffffffu, ploss, off);
        psig  += __shfl_down_sync(0xffffffffu, psig, off);
    }
    if (lid == 0) { rwd1[wid] = ploss; rwd2[wid] = psig; }
    __syncthreads();
    double pos_loss = 0.0, pos_sig = 0.0;
    if (tid == 0) {
        #pragma unroll
        for (int w = 0; w < 8; w++) { pos_loss += rwd1[w]; pos_sig += rwd2[w]; }
        rwd1[0] = pos_loss; rwd2[0] = pos_sig;
    }
    __syncthreads();
    pos_loss = rwd1[0]; pos_sig = rwd2[0];

    // suffix scan of corrected counts
    long long l0 = s_cnt[4 * tid + 0], l1 = s_cnt[4 * tid + 1],
              l2 = s_cnt[4 * tid + 2], l3 = s_cnt[4 * tid + 3];
    s_scan[tid] = l0 + l1 + l2 + l3;
    __syncthreads();
    for (int off = 1; off < NTHR; off <<= 1) {
        long long v = (tid + off < NTHR) ? s_scan[tid + off] : 0;
        __syncthreads();
        s_scan[tid] += v;
        __syncthreads();
    }
    long long below = (tid + 1 < NTHR) ? s_scan[tid + 1] : 0;
    long long suf3 = l3 + below, suf2 = l2 + suf3, suf1 = l1 + suf2, suf0 = l0 + suf1;
    long long sufs[4] = {suf0, suf1, suf2, suf3};

    long long n_posL = (long long)n_pos;
    long long n_neg = (long long)n - n_posL;
    long long nhns = (n_posL > 0) ? min(n_posL * 30LL, n_neg)
                                  : (long long)(0.1 * (double)n_neg);
    long long cnt_above = (long long)g_cnt_above - (long long)sh_adj_cnt;

    #pragma unroll
    for (int c = 0; c < 4; c++) {
        int bin = 4 * tid + c;
        if (cnt_above + sufs[c] >= nhns) atomicMax(&sh_i0, bin);
    }
    __syncthreads();
    int bstar = sh_i0;
    if (bstar >= 0 && (bstar >> 2) == tid) sh_suf = sufs[bstar & 3];
    __syncthreads();

    double fl = 0.0, fs = 0.0;
    #pragma unroll
    for (int c = 0; c < 4; c++) {
        int bin = 4 * tid + c;
        if (bin > bstar) { fl += (double)s_loss[bin]; fs += (double)s_sig[bin]; }
    }
    for (int off = 16; off > 0; off >>= 1) {
        fl += __shfl_down_sync(0xffffffffu, fl, off);
        fs += __shfl_down_sync(0xffffffffu, fs, off);
    }
    if (lid == 0) { rwd1[wid] = fl; rwd2[wid] = fs; }
    __syncthreads();

    if (tid == 0) {
        double sfl = 0.0, sfs = 0.0;
        #pragma unroll
        for (int w = 0; w < 8; w++) { sfl += rwd1[w]; sfs += rwd2[w]; }
        double neg_loss = g_loss_above - sh_adj_loss + sfl;
        double neg_sig  = g_sig_above  - sh_adj_sig  + sfs;
        if (bstar >= 0 && bstar < FINE_BINS && s_cnt[bstar] > 0) {
            long long taken = cnt_above + (sh_suf - (long long)s_cnt[bstar]);
            long long r = nhns - taken;
            if (r < 0) r = 0;
            if (r > (long long)s_cnt[bstar]) r = (long long)s_cnt[bstar];
            double frac = (double)r / (double)s_cnt[bstar];
            neg_loss += frac * (double)s_loss[bstar];
            neg_sig  += frac * (double)s_sig[bstar];
        }
        double total_loss = neg_loss + pos_loss;
        double mean_loss  = total_loss / (double)(nhns + n_posL);
        double inter = pos_sig;
        double denom = neg_sig + pos_sig + (double)n_posL;
        double dice  = 1.0 - (2.0 * inter + 1e-10) / (denom + 1e-10);
        sh_result = (float)(dice + mean_loss);
    }
    __syncthreads();
    float r = sh_result;
    for (int i = tid; i < out_size; i += NTHR) out[i] = r;
}

// ---------------------------------------------------------------------------
extern "C" void kernel_launch(void* const* d_in, const int* in_sizes, int n_in,
                              void* d_out, int out_size) {
    const float* preds = (const float*)d_in[0];
    const int*   targs = (const int*)d_in[1];
    int n = in_sizes[0];

    k_init<<<1, 1024>>>();
    k_main<<<G, NTHR>>>(preds, targs, (float*)d_out, out_size, n);
}

// round 11
// speedup vs baseline: 2.5652x; 1.1185x over previous
#include <cuda_runtime.h>
#include <math.h>
#include <stdint.h>

#define G 296
#define NTHR 512
#define NWARP 16
#define STAGES 3
#define TILE_ELEMS 4096
#define TILE_BYTES 16384
#define TILE_V4 1024
#define SAMP_BINS 1024
#define FINE_BINS 1024
#define MAX_POS (1 << 20)
#define SAMP_LO (-12.0f)
#define SAMP_W  (24.0f / SAMP_BINS)
#define LBATCH 2            // float4/int4 pairs per thread per iter (LDG path)

static __device__ unsigned           g_bar;
static __device__ int                g_pos_n;
static __device__ float              g_pos_val[MAX_POS];
static __device__ int                g_samp_hist[SAMP_BINS];
static __device__ int                g_samp_pos;
static __device__ float              g_Tlo, g_Thi;
static __device__ unsigned long long g_cnt_above;
static __device__ double             g_loss_above, g_sig_above;
static __device__ int                g_fine_cnt[FINE_BINS];
static __device__ float              g_fine_loss[FINE_BINS];
static __device__ float              g_fine_sig[FINE_BINS];

__device__ __forceinline__ float softplus_acc(float x) {
    return fmaxf(x, 0.0f) + log1pf(__expf(-fabsf(x)));
}
// shared-exp fast path: 3 MUFU. Used identically in stream AND finale mirror.
__device__ __forceinline__ void fast_sp_sg(float v, float& sp, float& sg) {
    float e = __expf(-fabsf(v));
    float l = __logf(1.0f + e);
    float r = __fdividef(1.0f, 1.0f + e);
    sp = fmaxf(v, 0.0f) + l;
    sg = (v >= 0.0f) ? r : 1.0f - r;
}
__device__ __forceinline__ float sigm_fast(float x) {
    return __fdividef(1.0f, 1.0f + __expf(-x));
}

// ---- TMA helpers ----------------------------------------------------------
__device__ __forceinline__ uint32_t smaddr(const void* p) {
    return (uint32_t)__cvta_generic_to_shared(p);
}
__device__ __forceinline__ void mbar_init(uint32_t a, uint32_t cnt) {
    asm volatile("mbarrier.init.shared.b64 [%0], %1;" :: "r"(a), "r"(cnt) : "memory");
}
__device__ __forceinline__ void mbar_expect_tx(uint32_t a, uint32_t bytes) {
    asm volatile("mbarrier.arrive.expect_tx.shared.b64 _, [%0], %1;" :: "r"(a), "r"(bytes) : "memory");
}
__device__ __forceinline__ void bulk_g2s(uint32_t dst, const void* gsrc, uint32_t bytes, uint32_t mbar) {
    asm volatile(
        "cp.async.bulk.shared::cluster.global.mbarrier::complete_tx::bytes [%0], [%1], %2, [%3];"
        :: "r"(dst), "l"(gsrc), "r"(bytes), "r"(mbar) : "memory");
}
__device__ __forceinline__ void mbar_wait(uint32_t a, uint32_t parity) {
    asm volatile(
        "{\n\t"
        ".reg .pred P1;\n\t"
        "WAIT_LOOP_%=:\n\t"
        "mbarrier.try_wait.parity.acquire.cta.shared::cta.b64 P1, [%0], %1, 0x989680;\n\t"
        "@P1 bra.uni WAIT_DONE_%=;\n\t"
        "bra.uni WAIT_LOOP_%=;\n\t"
        "WAIT_DONE_%=:\n\t"
        "}"
        :: "r"(a), "r"(parity) : "memory");
}

__device__ __forceinline__ void grid_bar(int tid, unsigned target) {
    __syncthreads();
    if (tid == 0) {
        __threadfence();
        atomicAdd(&g_bar, 1u);
        while (atomicAdd(&g_bar, 0u) < target) __nanosleep(128);
        __threadfence();
    }
    __syncthreads();
}

// ---------------------------------------------------------------------------
__global__ void k_init() {
    int i = threadIdx.x;
    if (i == 0) {
        g_bar = 0u;
        g_pos_n = 0;
        g_samp_pos = 0;
        g_cnt_above = 0ull;
        g_loss_above = 0.0;
        g_sig_above = 0.0;
    }
    if (i < SAMP_BINS) g_samp_hist[i] = 0;
    if (i < FINE_BINS) {
        g_fine_cnt[i] = 0;
        g_fine_loss[i] = 0.0f;
        g_fine_sig[i] = 0.0f;
    }
}

// ---------------------------------------------------------------------------
// THE kernel: sample -> pick -> dual-path stream (TMA + LDG) -> finale
// 512 threads/CTA, 2 CTA/SM -> 32 warps/SM
// ---------------------------------------------------------------------------
__global__ __launch_bounds__(NTHR, 2) void k_main(
    const float* __restrict__ preds, const int* __restrict__ targs,
    float* __restrict__ out, int out_size, int n)
{
    __shared__ alignas(128) float4 bufP[STAGES][TILE_V4];   // 48KB
    __shared__ alignas(128) int4   bufT[STAGES][TILE_V4];   // 48KB
    __shared__ uint64_t  mbar[STAGES];
    __shared__ int       s_cnt[FINE_BINS];                  // also sample hist
    __shared__ float     s_loss[FINE_BINS];
    __shared__ float     s_sig[FINE_BINS];
    __shared__ long long s_scan[NTHR];
    __shared__ int       rwc[NWARP];
    __shared__ float     rwl[NWARP], rws[NWARP];
    __shared__ double    rwd1[NWARP], rwd2[NWARP];
    __shared__ int       sh_i0, sh_i1;
    __shared__ long long sh_suf;
    __shared__ double    sh_adj_loss, sh_adj_sig;
    __shared__ int       sh_adj_cnt;
    __shared__ float     sh_result;

    const int tid = threadIdx.x;
    const int b0  = blockIdx.x;
    const int wid = tid >> 5, lid = tid & 31;

    const int ntiles = n / TILE_ELEMS;
    const int t_tiles = ntiles >> 1;                  // TMA region: first half
    const int np = (t_tiles > b0) ? (t_tiles - b0 + G - 1) / G : 0;

    const int n4 = n >> 2;
    const int l4base = t_tiles * (TILE_ELEMS / 4);    // LDG region start (v4)
    const int lspan = G * NTHR;                       // v4 per j-step chip-wide
    const int lchunk = lspan * LBATCH;                // v4 per iteration chip-wide
    const int ldg_v4 = n4 - l4base;
    const int liters = (ldg_v4 + lchunk - 1) / lchunk;
    const int IT = (np > liters) ? np : liters;

    if (tid == 0) {
        #pragma unroll
        for (int s = 0; s < STAGES; s++) mbar_init(smaddr(&mbar[s]), 1);
        asm volatile("fence.proxy.async.shared::cta;" ::: "memory");
    }
    for (int i = tid; i < SAMP_BINS; i += NTHR) s_cnt[i] = 0;   // sample hist
    __syncthreads();

    // prefetch STAGES tile-pairs of the TMA region
    if (tid == 0) {
        #pragma unroll
        for (int li = 0; li < STAGES; li++) {
            if (li < np) {
                int g = b0 + li * G;
                uint32_t mb = smaddr(&mbar[li]);
                mbar_expect_tx(mb, 2 * TILE_BYTES);
                bulk_g2s(smaddr(&bufP[li][0]), (const char*)preds + (size_t)g * TILE_BYTES, TILE_BYTES, mb);
                bulk_g2s(smaddr(&bufT[li][0]), (const char*)targs + (size_t)g * TILE_BYTES, TILE_BYTES, mb);
            }
        }
    }

    // ================= phase A: coalesced 1/32 sample =================
    {
        const int nseg = n4 / (32 * NTHR);
        const float scale = (float)SAMP_BINS / 24.0f;
        int myp = 0;
        const float4* preds4 = (const float4*)preds;
        const int4*   targs4 = (const int4*)targs;
        for (int s = b0; s < nseg; s += G) {
            int idx4 = s * 32 * NTHR + tid;
            float4 p = __ldcs(&preds4[idx4]);
            int4   t = __ldcs(&targs4[idx4]);
            if (!t.x) { int b = (int)((p.x - SAMP_LO) * scale); b = max(0, min(SAMP_BINS - 1, b)); atomicAdd(&s_cnt[b], 1); } else myp++;
            if (!t.y) { int b = (int)((p.y - SAMP_LO) * scale); b = max(0, min(SAMP_BINS - 1, b)); atomicAdd(&s_cnt[b], 1); } else myp++;
            if (!t.z) { int b = (int)((p.z - SAMP_LO) * scale); b = max(0, min(SAMP_BINS - 1, b)); atomicAdd(&s_cnt[b], 1); } else myp++;
            if (!t.w) { int b = (int)((p.w - SAMP_LO) * scale); b = max(0, min(SAMP_BINS - 1, b)); atomicAdd(&s_cnt[b], 1); } else myp++;
        }
        if (myp) atomicAdd(&g_samp_pos, myp);
        __syncthreads();
        for (int i = tid; i < SAMP_BINS; i += NTHR) {
            int c = s_cnt[i];
            if (c) atomicAdd(&g_samp_hist[i], c);
        }
    }
    grid_bar(tid, G);

    // ================= phase B: pick window (CTA 0, 2 bins/thread) ==========
    if (b0 == 0) {
        long long loc0 = __ldcg(&g_samp_hist[2 * tid + 0]);
        long long loc1 = __ldcg(&g_samp_hist[2 * tid + 1]);
        if (tid == 0) { sh_i0 = SAMP_BINS; sh_i1 = -1; }
        s_scan[tid] = loc0 + loc1;
        __syncthreads();
        for (int off = 1; off < NTHR; off <<= 1) {
            long long v = (tid + off < NTHR) ? s_scan[tid + off] : 0;
            __syncthreads();
            s_scan[tid] += v;
            __syncthreads();
        }
        long long below = (tid + 1 < NTHR) ? s_scan[tid + 1] : 0;
        long long suf1 = loc1 + below, suf0 = loc0 + suf1;

        long long pos_est = 32LL * (long long)__ldcg(&g_samp_pos);
        long long neg_est = (long long)n - pos_est;
        long long nhns = (pos_est > 0) ? min(pos_est * 30LL, neg_est)
                                       : (long long)(0.1 * (double)neg_est);
        long long sufs[2] = {suf0, suf1};
        #pragma unroll
        for (int c = 0; c < 2; c++) {
            int bin = 2 * tid + c;
            long long est = 32LL * sufs[c];
            if (est * 100 <= nhns * 65) atomicMin(&sh_i0, bin);
            if (est * 10  >= nhns * 15) atomicMax(&sh_i1, bin);
        }
        __syncthreads();
        if (tid == 0) {
            int bhi = sh_i0, blo = sh_i1;
            if (bhi > SAMP_BINS - 1) bhi = SAMP_BINS - 1;
            if (bhi < 1) bhi = 1;
            if (blo < 0) blo = 0;
            if (blo >= bhi) blo = bhi - 1;
            g_Thi = SAMP_LO + (float)bhi * SAMP_W;
            g_Tlo = SAMP_LO + (float)blo * SAMP_W;
            __threadfence();
        }
    }
    grid_bar(tid, 2 * G);

    // ================= phase C: dual-path stream =================
    const float Tlo = __ldcg(&g_Tlo), Thi = __ldcg(&g_Thi);
    const float fscale = (float)FINE_BINS / (Thi - Tlo);
    for (int i = tid; i < FINE_BINS; i += NTHR) {
        s_cnt[i] = 0; s_loss[i] = 0.0f; s_sig[i] = 0.0f;
    }
    __syncthreads();

    int cnt = 0;
    float ls = 0.0f, ss = 0.0f;
    const float4* preds4 = (const float4*)preds;
    const int4*   targs4 = (const int4*)targs;

    auto proc_val = [&](float v) {
        if (v > Tlo) {
            float sp, sg;
            fast_sp_sg(v, sp, sg);
            if (v > Thi) {
                cnt++; ls += sp; ss += sg;
            } else {
                int fb = min((int)((v - Tlo) * fscale), FINE_BINS - 1);
                atomicAdd(&s_cnt[fb], 1);
                atomicAdd(&s_loss[fb], sp);
                atomicAdd(&s_sig[fb], sg);
            }
        }
    };
    auto proc_pos4 = [&](int4 a, float4 pv) {
        if (a.x | a.y | a.z | a.w) {
            if (a.x) { int d = atomicAdd(&g_pos_n, 1); if (d < MAX_POS) g_pos_val[d] = pv.x; }
            if (a.y) { int d = atomicAdd(&g_pos_n, 1); if (d < MAX_POS) g_pos_val[d] = pv.y; }
            if (a.z) { int d = atomicAdd(&g_pos_n, 1); if (d < MAX_POS) g_pos_val[d] = pv.z; }
            if (a.w) { int d = atomicAdd(&g_pos_n, 1); if (d < MAX_POS) g_pos_val[d] = pv.w; }
        }
    };

    for (int it = 0; it < IT; it++) {
        // ---- fire the LDG batch (flies during TMA consume) ----
        float4 lp[LBATCH];
        int4   lt[LBATCH];
        bool lact = (it < liters);
        int base4 = l4base + it * lchunk + b0 * NTHR + tid;
        #pragma unroll
        for (int j = 0; j < LBATCH; j++) {
            int idx4 = base4 + j * lspan;
            if (lact && idx4 < n4) {
                lp[j] = __ldcs(&preds4[idx4]);
                lt[j] = __ldcs(&targs4[idx4]);
            } else {
                lp[j] = make_float4(-1e30f, -1e30f, -1e30f, -1e30f);
                lt[j] = make_int4(0, 0, 0, 0);
            }
        }

        // ---- TMA pair for this iteration (2 v4 per thread at 512 thr) ----
        if (it < np) {
            int slot = it % STAGES;
            int parity = (it / STAGES) & 1;
            mbar_wait(smaddr(&mbar[slot]), parity);

            #pragma unroll
            for (int k = 0; k < 2; k++) {
                float4 p = bufP[slot][tid + k * NTHR];
                proc_val(p.x); proc_val(p.y); proc_val(p.z); proc_val(p.w);
            }
            #pragma unroll
            for (int k = 0; k < 2; k++) {
                int v = tid + k * NTHR;
                int4 a = bufT[slot][v];
                if (a.x | a.y | a.z | a.w) proc_pos4(a, bufP[slot][v]);
            }
            __syncthreads();   // pair fully consumed

            if (tid == 0 && it + STAGES < np) {
                int g = b0 + (it + STAGES) * G;
                uint32_t mb = smaddr(&mbar[slot]);
                mbar_expect_tx(mb, 2 * TILE_BYTES);
                bulk_g2s(smaddr(&bufP[slot][0]), (const char*)preds + (size_t)g * TILE_BYTES, TILE_BYTES, mb);
                bulk_g2s(smaddr(&bufT[slot][0]), (const char*)targs + (size_t)g * TILE_BYTES, TILE_BYTES, mb);
            }
        }

        // ---- process the LDG batch (next TMA already in flight) ----
        #pragma unroll
        for (int j = 0; j < LBATCH; j++) {
            float4 p = lp[j];
            proc_val(p.x); proc_val(p.y); proc_val(p.z); proc_val(p.w);
            proc_pos4(lt[j], p);
        }
    }

    // tail elements (n not multiple of TILE_ELEMS): CTA 0
    if (b0 == 0) {
        for (int i = ntiles * TILE_ELEMS + tid; i < n; i += NTHR) {
            float v = preds[i];
            proc_val(v);
            if (targs[i]) {
                int d = atomicAdd(&g_pos_n, 1);
                if (d < MAX_POS) g_pos_val[d] = v;
            }
        }
    }

    // merge above-threshold sums
    for (int off = 16; off > 0; off >>= 1) {
        cnt += __shfl_down_sync(0xffffffffu, cnt, off);
        ls  += __shfl_down_sync(0xffffffffu, ls, off);
        ss  += __shfl_down_sync(0xffffffffu, ss, off);
    }
    if (lid == 0) { rwc[wid] = cnt; rwl[wid] = ls; rws[wid] = ss; }
    __syncthreads();
    if (tid == 0) {
        int tc = 0; float tl = 0.0f, ts = 0.0f;
        #pragma unroll
        for (int w = 0; w < NWARP; w++) { tc += rwc[w]; tl += rwl[w]; ts += rws[w]; }
        if (tc) atomicAdd(&g_cnt_above, (unsigned long long)tc);
        atomicAdd(&g_loss_above, (double)tl);
        atomicAdd(&g_sig_above,  (double)ts);
    }
    for (int i = tid; i < FINE_BINS; i += NTHR) {
        int c = s_cnt[i];
        if (c) {
            atomicAdd(&g_fine_cnt[i], c);
            atomicAdd(&g_fine_loss[i], s_loss[i]);
            atomicAdd(&g_fine_sig[i], s_sig[i]);
        }
    }
    grid_bar(tid, 3 * G);

    // ================= phase D: finale (CTA 0, 2 bins/thread) ==============
    if (b0 != 0) return;

    for (int c = 0; c < 2; c++) {
        int bin = 2 * tid + c;
        s_cnt[bin]  = __ldcg(&g_fine_cnt[bin]);
        s_loss[bin] = __ldcg(&g_fine_loss[bin]);
        s_sig[bin]  = __ldcg(&g_fine_sig[bin]);
    }
    if (tid == 0) { sh_adj_cnt = 0; sh_adj_loss = 0.0; sh_adj_sig = 0.0; sh_i0 = -1; }
    __syncthreads();

    int n_pos = min(__ldcg(&g_pos_n), MAX_POS);

    double ploss = 0.0, psig = 0.0;
    for (int i = tid; i < n_pos; i += NTHR) {
        float q  = __ldcg(&g_pos_val[i]);
        float sp_a = softplus_acc(q);
        float sg_a = sigm_fast(q);
        ploss += (double)(sp_a - q);
        psig  += (double)sg_a;
        if (q > Tlo) {
            float spf, sgf;
            fast_sp_sg(q, spf, sgf);     // EXACT mirror of stream fast path
            if (q > Thi) {
                atomicAdd(&sh_adj_cnt, 1);
                atomicAdd(&sh_adj_loss, (double)spf);
                atomicAdd(&sh_adj_sig,  (double)sgf);
            } else {
                int fb = min((int)((q - Tlo) * fscale), FINE_BINS - 1);
                atomicSub(&s_cnt[fb], 1);
                atomicAdd(&s_loss[fb], -spf);
                atomicAdd(&s_sig[fb],  -sgf);
            }
        }
    }
    for (int off = 16; off > 0; off >>= 1) {
        ploss += __shfl_down_sync(0xffffffffu, ploss, off);
        psig  += __shfl_down_sync(0xffffffffu, psig, off);
    }
    if (lid == 0) { rwd1[wid] = ploss; rwd2[wid] = psig; }
    __syncthreads();
    double pos_loss = 0.0, pos_sig = 0.0;
    if (tid == 0) {
        #pragma unroll
        for (int w = 0; w < NWARP; w++) { pos_loss += rwd1[w]; pos_sig += rwd2[w]; }
        rwd1[0] = pos_loss; rwd2[0] = pos_sig;
    }
    __syncthreads();
    pos_loss = rwd1[0]; pos_sig = rwd2[0];

    // suffix scan of corrected counts
    long long l0 = s_cnt[2 * tid + 0], l1 = s_cnt[2 * tid + 1];
    s_scan[tid] = l0 + l1;
    __syncthreads();
    for (int off = 1; off < NTHR; off <<= 1) {
        long long v = (tid + off < NTHR) ? s_scan[tid + off] : 0;
        __syncthreads();
        s_scan[tid] += v;
        __syncthreads();
    }
    long long below = (tid + 1 < NTHR) ? s_scan[tid + 1] : 0;
    long long suf1 = l1 + below, suf0 = l0 + suf1;
    long long sufs[2] = {suf0, suf1};

    long long n_posL = (long long)n_pos;
    long long n_neg = (long long)n - n_posL;
    long long nhns = (n_posL > 0) ? min(n_posL * 30LL, n_neg)
                                  : (long long)(0.1 * (double)n_neg);
    long long cnt_above = (long long)g_cnt_above - (long long)sh_adj_cnt;

    #pragma unroll
    for (int c = 0; c < 2; c++) {
        int bin = 2 * tid + c;
        if (cnt_above + sufs[c] >= nhns) atomicMax(&sh_i0, bin);
    }
    __syncthreads();
    int bstar = sh_i0;
    if (bstar >= 0 && (bstar >> 1) == tid) sh_suf = sufs[bstar & 1];
    __syncthreads();

    double fl = 0.0, fs = 0.0;
    #pragma unroll
    for (int c = 0; c < 2; c++) {
        int bin = 2 * tid + c;
        if (bin > bstar) { fl += (double)s_loss[bin]; fs += (double)s_sig[bin]; }
    }
    for (int off = 16; off > 0; off >>= 1) {
        fl += __shfl_down_sync(0xffffffffu, fl, off);
        fs += __shfl_down_sync(0xffffffffu, fs, off);
    }
    if (lid == 0) { rwd1[wid] = fl; rwd2[wid] = fs; }
    __syncthreads();

    if (tid == 0) {
        double sfl = 0.0, sfs = 0.0;
        #pragma unroll
        for (int w = 0; w < NWARP; w++) { sfl += rwd1[w]; sfs += rwd2[w]; }
        double neg_loss = g_loss_above - sh_adj_loss + sfl;
        double neg_sig  = g_sig_above  - sh_adj_sig  + sfs;
        if (bstar >= 0 && bstar < FINE_BINS && s_cnt[bstar] > 0) {
            long long taken = cnt_above + (sh_suf - (long long)s_cnt[bstar]);
            long long r = nhns - taken;
            if (r < 0) r = 0;
            if (r > (long long)s_cnt[bstar]) r = (long long)s_cnt[bstar];
            double frac = (double)r / (double)s_cnt[bstar];
            neg_loss += frac * (double)s_loss[bstar];
            neg_sig  += frac * (double)s_sig[bstar];
        }
        double total_loss = neg_loss + pos_loss;
        double mean_loss  = total_loss / (double)(nhns + n_posL);
        double inter = pos_sig;
        double denom = neg_sig + pos_sig + (double)n_posL;
        double dice  = 1.0 - (2.0 * inter + 1e-10) / (denom + 1e-10);
        sh_result = (float)(dice + mean_loss);
    }
    __syncthreads();
    float r = sh_result;
    for (int i = tid; i < out_size; i += NTHR) out[i] = r;
}

// ---------------------------------------------------------------------------
extern "C" void kernel_launch(void* const* d_in, const int* in_sizes, int n_in,
                              void* d_out, int out_size) {
    const float* preds = (const float*)d_in[0];
    const int*   targs = (const int*)d_in[1];
    int n = in_sizes[0];

    k_init<<<1, 1024>>>();
    k_main<<<G, NTHR>>>(preds, targs, (float*)d_out, out_size, n);
}

// round 12
// speedup vs baseline: 2.7232x; 1.0616x over previous
#include <cuda_runtime.h>
#include <math.h>
#include <stdint.h>

#define G 444                   // 3 CTAs/SM x 148 SMs
#define NTHR 512
#define NWARP 16
#define SAMP_BINS 1024
#define FINE_BINS 1024
#define MAX_POS (1 << 20)
#define SAMP_LO (-12.0f)
#define SAMP_W  (24.0f / SAMP_BINS)
#define LBATCH 2                // float4+int4 pairs per thread per iteration

static __device__ unsigned           g_bar;
static __device__ int                g_pos_n;
static __device__ float              g_pos_val[MAX_POS];
static __device__ int                g_samp_hist[SAMP_BINS];
static __device__ int                g_samp_pos;
static __device__ float              g_Tlo, g_Thi;
static __device__ unsigned long long g_cnt_above;
static __device__ double             g_loss_above, g_sig_above;
static __device__ int                g_fine_cnt[FINE_BINS];
static __device__ float              g_fine_loss[FINE_BINS];
static __device__ float              g_fine_sig[FINE_BINS];

__device__ __forceinline__ float softplus_acc(float x) {
    return fmaxf(x, 0.0f) + log1pf(__expf(-fabsf(x)));
}
// shared-exp fast path: 3 MUFU. Used identically in stream AND finale mirror.
__device__ __forceinline__ void fast_sp_sg(float v, float& sp, float& sg) {
    float e = __expf(-fabsf(v));
    float l = __logf(1.0f + e);
    float r = __fdividef(1.0f, 1.0f + e);
    sp = fmaxf(v, 0.0f) + l;
    sg = (v >= 0.0f) ? r : 1.0f - r;
}
__device__ __forceinline__ float sigm_fast(float x) {
    return __fdividef(1.0f, 1.0f + __expf(-x));
}

__device__ __forceinline__ void grid_bar(int tid, unsigned target) {
    __syncthreads();
    if (tid == 0) {
        __threadfence();
        atomicAdd(&g_bar, 1u);
        while (atomicAdd(&g_bar, 0u) < target) __nanosleep(128);
        __threadfence();
    }
    __syncthreads();
}

// ---------------------------------------------------------------------------
__global__ void k_init() {
    int i = threadIdx.x;
    if (i == 0) {
        g_bar = 0u;
        g_pos_n = 0;
        g_samp_pos = 0;
        g_cnt_above = 0ull;
        g_loss_above = 0.0;
        g_sig_above = 0.0;
    }
    if (i < SAMP_BINS) g_samp_hist[i] = 0;
    if (i < FINE_BINS) {
        g_fine_cnt[i] = 0;
        g_fine_loss[i] = 0.0f;
        g_fine_sig[i] = 0.0f;
    }
}

// ---------------------------------------------------------------------------
// THE kernel: sample -> pick -> pure-LDG stream -> finale.
// 512 thr/CTA, 3 CTA/SM -> 48 warps/SM. No TMA, no smem staging.
// ---------------------------------------------------------------------------
__global__ __launch_bounds__(NTHR, 3) void k_main(
    const float* __restrict__ preds, const int* __restrict__ targs,
    float* __restrict__ out, int out_size, int n)
{
    __shared__ int       s_cnt[FINE_BINS];                  // also sample hist
    __shared__ float     s_loss[FINE_BINS];
    __shared__ float     s_sig[FINE_BINS];
    __shared__ long long s_scan[NTHR];
    __shared__ int       rwc[NWARP];
    __shared__ float     rwl[NWARP], rws[NWARP];
    __shared__ double    rwd1[NWARP], rwd2[NWARP];
    __shared__ int       sh_i0, sh_i1;
    __shared__ long long sh_suf;
    __shared__ double    sh_adj_loss, sh_adj_sig;
    __shared__ int       sh_adj_cnt;
    __shared__ float     sh_result;

    const int tid = threadIdx.x;
    const int b0  = blockIdx.x;
    const int wid = tid >> 5, lid = tid & 31;
    const int n4 = n >> 2;
    const float4* preds4 = (const float4*)preds;
    const int4*   targs4 = (const int4*)targs;

    for (int i = tid; i < SAMP_BINS; i += NTHR) s_cnt[i] = 0;   // sample hist
    __syncthreads();

    // ================= phase A: coalesced 1/32 sample =================
    {
        const int nseg = n4 / (32 * NTHR);
        const float scale = (float)SAMP_BINS / 24.0f;
        int myp = 0;
        for (int s = b0; s < nseg; s += G) {
            int idx4 = s * 32 * NTHR + tid;
            float4 p = __ldcs(&preds4[idx4]);
            int4   t = __ldcs(&targs4[idx4]);
            if (!t.x) { int b = (int)((p.x - SAMP_LO) * scale); b = max(0, min(SAMP_BINS - 1, b)); atomicAdd(&s_cnt[b], 1); } else myp++;
            if (!t.y) { int b = (int)((p.y - SAMP_LO) * scale); b = max(0, min(SAMP_BINS - 1, b)); atomicAdd(&s_cnt[b], 1); } else myp++;
            if (!t.z) { int b = (int)((p.z - SAMP_LO) * scale); b = max(0, min(SAMP_BINS - 1, b)); atomicAdd(&s_cnt[b], 1); } else myp++;
            if (!t.w) { int b = (int)((p.w - SAMP_LO) * scale); b = max(0, min(SAMP_BINS - 1, b)); atomicAdd(&s_cnt[b], 1); } else myp++;
        }
        if (myp) atomicAdd(&g_samp_pos, myp);
        __syncthreads();
        for (int i = tid; i < SAMP_BINS; i += NTHR) {
            int c = s_cnt[i];
            if (c) atomicAdd(&g_samp_hist[i], c);
        }
    }
    grid_bar(tid, G);

    // ================= phase B: pick window (CTA 0, 2 bins/thread) ==========
    if (b0 == 0) {
        long long loc0 = __ldcg(&g_samp_hist[2 * tid + 0]);
        long long loc1 = __ldcg(&g_samp_hist[2 * tid + 1]);
        if (tid == 0) { sh_i0 = SAMP_BINS; sh_i1 = -1; }
        s_scan[tid] = loc0 + loc1;
        __syncthreads();
        for (int off = 1; off < NTHR; off <<= 1) {
            long long v = (tid + off < NTHR) ? s_scan[tid + off] : 0;
            __syncthreads();
            s_scan[tid] += v;
            __syncthreads();
        }
        long long below = (tid + 1 < NTHR) ? s_scan[tid + 1] : 0;
        long long suf1 = loc1 + below, suf0 = loc0 + suf1;

        long long pos_est = 32LL * (long long)__ldcg(&g_samp_pos);
        long long neg_est = (long long)n - pos_est;
        long long nhns = (pos_est > 0) ? min(pos_est * 30LL, neg_est)
                                       : (long long)(0.1 * (double)neg_est);
        long long sufs[2] = {suf0, suf1};
        #pragma unroll
        for (int c = 0; c < 2; c++) {
            int bin = 2 * tid + c;
            long long est = 32LL * sufs[c];
            if (est * 100 <= nhns * 65) atomicMin(&sh_i0, bin);
            if (est * 10  >= nhns * 15) atomicMax(&sh_i1, bin);
        }
        __syncthreads();
        if (tid == 0) {
            int bhi = sh_i0, blo = sh_i1;
            if (bhi > SAMP_BINS - 1) bhi = SAMP_BINS - 1;
            if (bhi < 1) bhi = 1;
            if (blo < 0) blo = 0;
            if (blo >= bhi) blo = bhi - 1;
            g_Thi = SAMP_LO + (float)bhi * SAMP_W;
            g_Tlo = SAMP_LO + (float)blo * SAMP_W;
            __threadfence();
        }
    }
    grid_bar(tid, 2 * G);

    // ================= phase C: pure-LDG stream =================
    const float Tlo = __ldcg(&g_Tlo), Thi = __ldcg(&g_Thi);
    const float fscale = (float)FINE_BINS / (Thi - Tlo);
    for (int i = tid; i < FINE_BINS; i += NTHR) {
        s_cnt[i] = 0; s_loss[i] = 0.0f; s_sig[i] = 0.0f;
    }
    __syncthreads();

    int cnt = 0;
    float ls = 0.0f, ss = 0.0f;

    auto proc_val = [&](float v) {
        if (v > Tlo) {
            float sp, sg;
            fast_sp_sg(v, sp, sg);
            if (v > Thi) {
                cnt++; ls += sp; ss += sg;
            } else {
                int fb = min((int)((v - Tlo) * fscale), FINE_BINS - 1);
                atomicAdd(&s_cnt[fb], 1);
                atomicAdd(&s_loss[fb], sp);
                atomicAdd(&s_sig[fb], sg);
            }
        }
    };
    auto proc_pos4 = [&](int4 a, float4 pv) {
        if (a.x | a.y | a.z | a.w) {
            if (a.x) { int d = atomicAdd(&g_pos_n, 1); if (d < MAX_POS) g_pos_val[d] = pv.x; }
            if (a.y) { int d = atomicAdd(&g_pos_n, 1); if (d < MAX_POS) g_pos_val[d] = pv.y; }
            if (a.z) { int d = atomicAdd(&g_pos_n, 1); if (d < MAX_POS) g_pos_val[d] = pv.z; }
            if (a.w) { int d = atomicAdd(&g_pos_n, 1); if (d < MAX_POS) g_pos_val[d] = pv.w; }
        }
    };

    {
        const int lspan = G * NTHR;             // v4 stride between batch slots
        const int lchunk = lspan * LBATCH;      // v4 per iteration chip-wide
        int base4 = b0 * NTHR + tid;
        for (; base4 + (LBATCH - 1) * lspan < n4; base4 += lchunk) {
            float4 lp[LBATCH];
            int4   lt[LBATCH];
            #pragma unroll
            for (int j = 0; j < LBATCH; j++) {
                int idx4 = base4 + j * lspan;
                lp[j] = __ldcs(&preds4[idx4]);
                lt[j] = __ldcs(&targs4[idx4]);
            }
            #pragma unroll
            for (int j = 0; j < LBATCH; j++) {
                float4 p = lp[j];
                proc_val(p.x); proc_val(p.y); proc_val(p.z); proc_val(p.w);
                proc_pos4(lt[j], p);
            }
        }
        // ragged end of the batched region
        for (; base4 < n4; base4 += lspan) {
            float4 p = __ldcs(&preds4[base4]);
            int4   t = __ldcs(&targs4[base4]);
            proc_val(p.x); proc_val(p.y); proc_val(p.z); proc_val(p.w);
            proc_pos4(t, p);
        }
    }

    // tail elements (n % 4): CTA 0
    if (b0 == 0) {
        for (int i = 4 * n4 + tid; i < n; i += NTHR) {
            float v = preds[i];
            proc_val(v);
            if (targs[i]) {
                int d = atomicAdd(&g_pos_n, 1);
                if (d < MAX_POS) g_pos_val[d] = v;
            }
        }
    }

    // merge above-threshold sums
    for (int off = 16; off > 0; off >>= 1) {
        cnt += __shfl_down_sync(0xffffffffu, cnt, off);
        ls  += __shfl_down_sync(0xffffffffu, ls, off);
        ss  += __shfl_down_sync(0xffffffffu, ss, off);
    }
    if (lid == 0) { rwc[wid] = cnt; rwl[wid] = ls; rws[wid] = ss; }
    __syncthreads();
    if (tid == 0) {
        int tc = 0; float tl = 0.0f, ts = 0.0f;
        #pragma unroll
        for (int w = 0; w < NWARP; w++) { tc += rwc[w]; tl += rwl[w]; ts += rws[w]; }
        if (tc) atomicAdd(&g_cnt_above, (unsigned long long)tc);
        atomicAdd(&g_loss_above, (double)tl);
        atomicAdd(&g_sig_above,  (double)ts);
    }
    for (int i = tid; i < FINE_BINS; i += NTHR) {
        int c = s_cnt[i];
        if (c) {
            atomicAdd(&g_fine_cnt[i], c);
            atomicAdd(&g_fine_loss[i], s_loss[i]);
            atomicAdd(&g_fine_sig[i], s_sig[i]);
        }
    }
    grid_bar(tid, 3 * G);

    // ================= phase D: finale (CTA 0, 2 bins/thread) ==============
    if (b0 != 0) return;

    for (int c = 0; c < 2; c++) {
        int bin = 2 * tid + c;
        s_cnt[bin]  = __ldcg(&g_fine_cnt[bin]);
        s_loss[bin] = __ldcg(&g_fine_loss[bin]);
        s_sig[bin]  = __ldcg(&g_fine_sig[bin]);
    }
    if (tid == 0) { sh_adj_cnt = 0; sh_adj_loss = 0.0; sh_adj_sig = 0.0; sh_i0 = -1; }
    __syncthreads();

    int n_pos = min(__ldcg(&g_pos_n), MAX_POS);

    double ploss = 0.0, psig = 0.0;
    for (int i = tid; i < n_pos; i += NTHR) {
        float q  = __ldcg(&g_pos_val[i]);
        float sp_a = softplus_acc(q);
        float sg_a = sigm_fast(q);
        ploss += (double)(sp_a - q);
        psig  += (double)sg_a;
        if (q > Tlo) {
            float spf, sgf;
            fast_sp_sg(q, spf, sgf);     // EXACT mirror of stream fast path
            if (q > Thi) {
                atomicAdd(&sh_adj_cnt, 1);
                atomicAdd(&sh_adj_loss, (double)spf);
                atomicAdd(&sh_adj_sig,  (double)sgf);
            } else {
                int fb = min((int)((q - Tlo) * fscale), FINE_BINS - 1);
                atomicSub(&s_cnt[fb], 1);
                atomicAdd(&s_loss[fb], -spf);
                atomicAdd(&s_sig[fb],  -sgf);
            }
        }
    }
    for (int off = 16; off > 0; off >>= 1) {
        ploss += __shfl_down_sync(0xffffffffu, ploss, off);
        psig  += __shfl_down_sync(0xffffffffu, psig, off);
    }
    if (lid == 0) { rwd1[wid] = ploss; rwd2[wid] = psig; }
    __syncthreads();
    double pos_loss = 0.0, pos_sig = 0.0;
    if (tid == 0) {
        #pragma unroll
        for (int w = 0; w < NWARP; w++) { pos_loss += rwd1[w]; pos_sig += rwd2[w]; }
        rwd1[0] = pos_loss; rwd2[0] = pos_sig;
    }
    __syncthreads();
    pos_loss = rwd1[0]; pos_sig = rwd2[0];

    // suffix scan of corrected counts
    long long l0 = s_cnt[2 * tid + 0], l1 = s_cnt[2 * tid + 1];
    s_scan[tid] = l0 + l1;
    __syncthreads();
    for (int off = 1; off < NTHR; off <<= 1) {
        long long v = (tid + off < NTHR) ? s_scan[tid + off] : 0;
        __syncthreads();
        s_scan[tid] += v;
        __syncthreads();
    }
    long long below = (tid + 1 < NTHR) ? s_scan[tid + 1] : 0;
    long long suf1 = l1 + below, suf0 = l0 + suf1;
    long long sufs[2] = {suf0, suf1};

    long long n_posL = (long long)n_pos;
    long long n_neg = (long long)n - n_posL;
    long long nhns = (n_posL > 0) ? min(n_posL * 30LL, n_neg)
                                  : (long long)(0.1 * (double)n_neg);
    long long cnt_above = (long long)g_cnt_above - (long long)sh_adj_cnt;

    #pragma unroll
    for (int c = 0; c < 2; c++) {
        int bin = 2 * tid + c;
        if (cnt_above + sufs[c] >= nhns) atomicMax(&sh_i0, bin);
    }
    __syncthreads();
    int bstar = sh_i0;
    if (bstar >= 0 && (bstar >> 1) == tid) sh_suf = sufs[bstar & 1];
    __syncthreads();

    double fl = 0.0, fs = 0.0;
    #pragma unroll
    for (int c = 0; c < 2; c++) {
        int bin = 2 * tid + c;
        if (bin > bstar) { fl += (double)s_loss[bin]; fs += (double)s_sig[bin]; }
    }
    for (int off = 16; off > 0; off >>= 1) {
        fl += __shfl_down_sync(0xffffffffu, fl, off);
        fs += __shfl_down_sync(0xffffffffu, fs, off);
    }
    if (lid == 0) { rwd1[wid] = fl; rwd2[wid] = fs; }
    __syncthreads();

    if (tid == 0) {
        double sfl = 0.0, sfs = 0.0;
        #pragma unroll
        for (int w = 0; w < NWARP; w++) { sfl += rwd1[w]; sfs += rwd2[w]; }
        double neg_loss = g_loss_above - sh_adj_loss + sfl;
        double neg_sig  = g_sig_above  - sh_adj_sig  + sfs;
        if (bstar >= 0 && bstar < FINE_BINS && s_cnt[bstar] > 0) {
            long long taken = cnt_above + (sh_suf - (long long)s_cnt[bstar]);
            long long r = nhns - taken;
            if (r < 0) r = 0;
            if (r > (long long)s_cnt[bstar]) r = (long long)s_cnt[bstar];
            double frac = (double)r / (double)s_cnt[bstar];
            neg_loss += frac * (double)s_loss[bstar];
            neg_sig  += frac * (double)s_sig[bstar];
        }
        double total_loss = neg_loss + pos_loss;
        double mean_loss  = total_loss / (double)(nhns + n_posL);
        double inter = pos_sig;
        double denom = neg_sig + pos_sig + (double)n_posL;
        double dice  = 1.0 - (2.0 * inter + 1e-10) / (denom + 1e-10);
        sh_result = (float)(dice + mean_loss);
    }
    __syncthreads();
    float r = sh_result;
    for (int i = tid; i < out_size; i += NTHR) out[i] = r;
}

// ---------------------------------------------------------------------------
extern "C" void kernel_launch(void* const* d_in, const int* in_sizes, int n_in,
                              void* d_out, int out_size) {
    const float* preds = (const float*)d_in[0];
    const int*   targs = (const int*)d_in[1];
    int n = in_sizes[0];

    k_init<<<1, 1024>>>();
    k_main<<<G, NTHR>>>(preds, targs, (float*)d_out, out_size, n);
}